// round 1
// baseline (speedup 1.0000x reference)
#include <cuda_runtime.h>
#include <cstdint>

#define DIM    1536
#define HEADS  12
#define HD     128
#define LTOK   3520
#define EPS    1e-6f
#define SCALE  0.08838834764831845f   // 1/sqrt(128)

// ---------------- scratch (no allocation allowed) ----------------
__device__ float g_q[LTOK * DIM];
__device__ float g_k[LTOK * DIM];
__device__ float g_v[LTOK * DIM];
__device__ float g_o[LTOK * DIM];

// ================= SGEMM: C[M,N] = A[M,K] @ B[N,K]^T + bias =================
#define BM 64
#define BN 64
#define BKK 16

__global__ void __launch_bounds__(256) sgemm_bias(
    const float* __restrict__ A, const float* __restrict__ B,
    const float* __restrict__ bias, float* __restrict__ C,
    int M, int N, int K)
{
    __shared__ float As[BKK][BM + 4];
    __shared__ float Bs[BKK][BN + 4];

    const int tid = threadIdx.x;
    const int tx = tid & 15;
    const int ty = tid >> 4;
    const int m0 = blockIdx.y * BM;
    const int n0 = blockIdx.x * BN;

    const int lrow = tid >> 2;          // 0..63
    const int lk   = (tid & 3) * 4;     // 0,4,8,12

    const float* ag = A + (size_t)(m0 + lrow) * K + lk;
    const float* bg = B + (size_t)(n0 + lrow) * K + lk;

    float acc[4][4] = {};

    for (int k0 = 0; k0 < K; k0 += BKK) {
        float4 av = *(const float4*)(ag + k0);
        float4 bv = *(const float4*)(bg + k0);
        As[lk + 0][lrow] = av.x; As[lk + 1][lrow] = av.y;
        As[lk + 2][lrow] = av.z; As[lk + 3][lrow] = av.w;
        Bs[lk + 0][lrow] = bv.x; Bs[lk + 1][lrow] = bv.y;
        Bs[lk + 2][lrow] = bv.z; Bs[lk + 3][lrow] = bv.w;
        __syncthreads();

#pragma unroll
        for (int kk = 0; kk < BKK; ++kk) {
            float4 a4 = *(const float4*)&As[kk][ty * 4];
            float4 b4 = *(const float4*)&Bs[kk][tx * 4];
            float ar[4] = {a4.x, a4.y, a4.z, a4.w};
            float br[4] = {b4.x, b4.y, b4.z, b4.w};
#pragma unroll
            for (int j = 0; j < 4; ++j)
#pragma unroll
                for (int i = 0; i < 4; ++i)
                    acc[j][i] += ar[j] * br[i];
        }
        __syncthreads();
    }

    float4 bb = *(const float4*)(bias + n0 + tx * 4);
    float bbr[4] = {bb.x, bb.y, bb.z, bb.w};
#pragma unroll
    for (int j = 0; j < 4; ++j) {
        float4 o;
        o.x = acc[j][0] + bbr[0];
        o.y = acc[j][1] + bbr[1];
        o.z = acc[j][2] + bbr[2];
        o.w = acc[j][3] + bbr[3];
        *(float4*)(C + (size_t)(m0 + ty * 4 + j) * N + n0 + tx * 4) = o;
    }
}

// ================= fused RMSNorm + RoPE (q and k) =================
__global__ void __launch_bounds__(256) rmsnorm_rope(
    const float* __restrict__ gq, const float* __restrict__ gk,
    const float* __restrict__ freqs, const int* __restrict__ gsz)
{
    const int t = blockIdx.x;
    const int which = blockIdx.y;         // 0=q, 1=k
    float* row = (which ? g_k : g_q) + (size_t)t * DIM;
    const float* g = which ? gk : gq;
    const int tid = threadIdx.x;

    // sum of squares over 1536
    float ss = 0.f;
    for (int i = tid; i < DIM; i += 256) {
        float v = row[i];
        ss += v * v;
    }
    __shared__ float red[8];
#pragma unroll
    for (int o = 16; o; o >>= 1) ss += __shfl_xor_sync(0xffffffffu, ss, o);
    if ((tid & 31) == 0) red[tid >> 5] = ss;
    __syncthreads();
    if (tid < 8) {
        float v = red[tid];
#pragma unroll
        for (int o = 4; o; o >>= 1) v += __shfl_xor_sync(0xffu, v, o);
        if (tid == 0) red[0] = v;
    }
    __syncthreads();
    const float rms = rsqrtf(red[0] * (1.0f / DIM) + EPS);

    const int Hs = gsz[1], Ws = gsz[2];
    const int fi = t / (Hs * Ws);
    const int hi = (t / Ws) % Hs;
    const int wi = t % Ws;

    // 12 heads * 64 pairs = 768 pairs
    for (int p = tid; p < HEADS * 64; p += 256) {
        const int h = p >> 6;
        const int j = p & 63;
        const int pos = (j < 22) ? fi : ((j < 43) ? hi : wi);
        const float ang = freqs[pos * 64 + j];
        float c, s;
        sincosf(ang, &s, &c);
        const int d0 = h * HD + 2 * j;
        const float x0 = row[d0]     * rms * g[d0];
        const float x1 = row[d0 + 1] * rms * g[d0 + 1];
        row[d0]     = x0 * c - x1 * s;
        row[d0 + 1] = x0 * s + x1 * c;
    }
}

// ================= flash attention (fp32) =================
#define BQ 64
#define BKT 64
#define QSTRIDE 132
#define SSTRIDE 68
// smem floats: Qs 64*132 + KVs 64*132 + Ss 64*68 + m/l/f 3*64
#define FLASH_SMEM_FLOATS (64 * QSTRIDE * 2 + 64 * SSTRIDE + 192)

__global__ void __launch_bounds__(256) flash_attn()
{
    extern __shared__ float sm[];
    float* Qs  = sm;
    float* KVs = Qs + 64 * QSTRIDE;
    float* Ss  = KVs + 64 * QSTRIDE;
    float* m_s = Ss + 64 * SSTRIDE;
    float* l_s = m_s + 64;
    float* f_s = l_s + 64;

    const int tid = threadIdx.x;
    const int tx = tid & 15;
    const int ty = tid >> 4;
    const int h  = blockIdx.y;
    const int q0 = blockIdx.x * BQ;

    // load Q tile (pre-scaled by SCALE)
    for (int i = tid; i < BQ * (HD / 4); i += 256) {
        const int r  = i >> 5;
        const int c4 = (i & 31) * 4;
        float4 v = *(const float4*)(g_q + (size_t)(q0 + r) * DIM + h * HD + c4);
        v.x *= SCALE; v.y *= SCALE; v.z *= SCALE; v.w *= SCALE;
        *(float4*)&Qs[r * QSTRIDE + c4] = v;
    }
    if (tid < 64) { m_s[tid] = -3.0e38f; l_s[tid] = 0.f; }

    float O[4][8] = {};

    for (int t0 = 0; t0 < LTOK; t0 += BKT) {
        __syncthreads();   // KVs reads from previous PV phase complete

        // load K tile
        for (int i = tid; i < BKT * (HD / 4); i += 256) {
            const int r  = i >> 5;
            const int c4 = (i & 31) * 4;
            *(float4*)&KVs[r * QSTRIDE + c4] =
                *(const float4*)(g_k + (size_t)(t0 + r) * DIM + h * HD + c4);
        }
        __syncthreads();

        // S = Q @ K^T  (4x4 microtile per thread)
        float Sreg[4][4] = {};
#pragma unroll 8
        for (int d = 0; d < HD; d += 4) {
            float4 qv[4], kv[4];
#pragma unroll
            for (int j = 0; j < 4; ++j)
                qv[j] = *(const float4*)&Qs[(ty * 4 + j) * QSTRIDE + d];
#pragma unroll
            for (int i = 0; i < 4; ++i)
                kv[i] = *(const float4*)&KVs[(tx * 4 + i) * QSTRIDE + d];
#pragma unroll
            for (int j = 0; j < 4; ++j)
#pragma unroll
                for (int i = 0; i < 4; ++i)
                    Sreg[j][i] += qv[j].x * kv[i].x + qv[j].y * kv[i].y +
                                  qv[j].z * kv[i].z + qv[j].w * kv[i].w;
        }
#pragma unroll
        for (int j = 0; j < 4; ++j)
#pragma unroll
            for (int i = 0; i < 4; ++i)
                Ss[(ty * 4 + j) * SSTRIDE + tx * 4 + i] = Sreg[j][i];
        __syncthreads();   // Ss ready, KVs free

        // --- phase: online softmax on Ss  +  load V tile into KVs ---
        for (int i = tid; i < BKT * (HD / 4); i += 256) {
            const int r  = i >> 5;
            const int c4 = (i & 31) * 4;
            *(float4*)&KVs[r * QSTRIDE + c4] =
                *(const float4*)(g_v + (size_t)(t0 + r) * DIM + h * HD + c4);
        }
        {
            const int row = tid >> 2;        // 0..63
            const int seg = tid & 3;         // 16 cols each
            const float mold = m_s[row];
            float vals[16];
            float tm = -3.0e38f;
#pragma unroll
            for (int c = 0; c < 16; ++c) {
                vals[c] = Ss[row * SSTRIDE + seg * 16 + c];
                tm = fmaxf(tm, vals[c]);
            }
            tm = fmaxf(tm, __shfl_xor_sync(0xffffffffu, tm, 1));
            tm = fmaxf(tm, __shfl_xor_sync(0xffffffffu, tm, 2));
            const float mnew = fmaxf(mold, tm);
            float psum = 0.f;
#pragma unroll
            for (int c = 0; c < 16; ++c) {
                const float p = __expf(vals[c] - mnew);
                Ss[row * SSTRIDE + seg * 16 + c] = p;
                psum += p;
            }
            psum += __shfl_xor_sync(0xffffffffu, psum, 1);
            psum += __shfl_xor_sync(0xffffffffu, psum, 2);
            if (seg == 0) {
                const float f = __expf(mold - mnew);
                f_s[row] = f;
                l_s[row] = l_s[row] * f + psum;
                m_s[row] = mnew;
            }
        }
        __syncthreads();

        // --- rescale O, accumulate O += P @ V ---
        float fr[4];
#pragma unroll
        for (int j = 0; j < 4; ++j) {
            fr[j] = f_s[ty * 4 + j];
#pragma unroll
            for (int i = 0; i < 8; ++i) O[j][i] *= fr[j];
        }
#pragma unroll 4
        for (int k = 0; k < BKT; ++k) {
            float p[4];
#pragma unroll
            for (int j = 0; j < 4; ++j) p[j] = Ss[(ty * 4 + j) * SSTRIDE + k];
            float4 v0 = *(const float4*)&KVs[k * QSTRIDE + tx * 8];
            float4 v1 = *(const float4*)&KVs[k * QSTRIDE + tx * 8 + 4];
#pragma unroll
            for (int j = 0; j < 4; ++j) {
                O[j][0] += p[j] * v0.x; O[j][1] += p[j] * v0.y;
                O[j][2] += p[j] * v0.z; O[j][3] += p[j] * v0.w;
                O[j][4] += p[j] * v1.x; O[j][5] += p[j] * v1.y;
                O[j][6] += p[j] * v1.z; O[j][7] += p[j] * v1.w;
            }
        }
    }

    // finalize: divide by l, write out
#pragma unroll
    for (int j = 0; j < 4; ++j) {
        const float inv = 1.0f / l_s[ty * 4 + j];
        float4 o0, o1;
        o0.x = O[j][0] * inv; o0.y = O[j][1] * inv;
        o0.z = O[j][2] * inv; o0.w = O[j][3] * inv;
        o1.x = O[j][4] * inv; o1.y = O[j][5] * inv;
        o1.z = O[j][6] * inv; o1.w = O[j][7] * inv;
        float* dst = g_o + (size_t)(q0 + ty * 4 + j) * DIM + h * HD + tx * 8;
        *(float4*)dst       = o0;
        *(float4*)(dst + 4) = o1;
    }
}

// ================= launch =================
extern "C" void kernel_launch(void* const* d_in, const int* in_sizes, int n_in,
                              void* d_out, int out_size)
{
    const float* x          = (const float*)d_in[0];
    // d_in[1] = seq_lens (unused; always full)
    const int*   grid_sizes = (const int*)d_in[2];
    const float* freqs      = (const float*)d_in[3];
    const float* Wq = (const float*)d_in[4];
    const float* bq = (const float*)d_in[5];
    const float* Wk = (const float*)d_in[6];
    const float* bk = (const float*)d_in[7];
    const float* Wv = (const float*)d_in[8];
    const float* bv = (const float*)d_in[9];
    const float* Wo = (const float*)d_in[10];
    const float* bo = (const float*)d_in[11];
    const float* gq = (const float*)d_in[12];
    const float* gk = (const float*)d_in[13];
    float* out = (float*)d_out;

    float *qp, *kp, *vp, *op;
    cudaGetSymbolAddress((void**)&qp, g_q);
    cudaGetSymbolAddress((void**)&kp, g_k);
    cudaGetSymbolAddress((void**)&vp, g_v);
    cudaGetSymbolAddress((void**)&op, g_o);

    const int smem_bytes = FLASH_SMEM_FLOATS * sizeof(float);
    cudaFuncSetAttribute(flash_attn, cudaFuncAttributeMaxDynamicSharedMemorySize, smem_bytes);

    dim3 gproj(DIM / BN, LTOK / BM);   // 24 x 55

    // QKV projections
    sgemm_bias<<<gproj, 256>>>(x, Wq, bq, qp, LTOK, DIM, DIM);
    sgemm_bias<<<gproj, 256>>>(x, Wk, bk, kp, LTOK, DIM, DIM);
    sgemm_bias<<<gproj, 256>>>(x, Wv, bv, vp, LTOK, DIM, DIM);

    // RMSNorm + RoPE on q and k
    rmsnorm_rope<<<dim3(LTOK, 2), 256>>>(gq, gk, freqs, grid_sizes);

    // attention
    flash_attn<<<dim3(LTOK / BQ, HEADS), 256, smem_bytes>>>();

    // output projection
    sgemm_bias<<<gproj, 256>>>(op, Wo, bo, out, LTOK, DIM, DIM);
}

// round 2
// speedup vs baseline: 4.0097x; 4.0097x over previous
#include <cuda_runtime.h>
#include <cstdint>

#define DIM    1536
#define HEADS  12
#define HD     128
#define LTOK   3520
#define EPS    1e-6f
#define SCALE  0.08838834764831845f   // 1/sqrt(128)

// ---------------- scratch (no allocation allowed) ----------------
__device__ float g_q[LTOK * DIM];
__device__ float g_k[LTOK * DIM];
__device__ float g_v[LTOK * DIM];
__device__ float g_o[LTOK * DIM];

// ---------------- tf32 helpers ----------------
__device__ __forceinline__ uint32_t f2tf(float f) {
    uint32_t u;
    asm("cvt.rna.tf32.f32 %0, %1;" : "=r"(u) : "f"(f));
    return u;
}

__device__ __forceinline__ void mma_tf32(float c[4],
    uint32_t a0, uint32_t a1, uint32_t a2, uint32_t a3,
    uint32_t b0, uint32_t b1)
{
    asm volatile(
        "mma.sync.aligned.m16n8k8.row.col.f32.tf32.tf32.f32 "
        "{%0,%1,%2,%3}, {%4,%5,%6,%7}, {%8,%9}, {%0,%1,%2,%3};\n"
        : "+f"(c[0]), "+f"(c[1]), "+f"(c[2]), "+f"(c[3])
        : "r"(a0), "r"(a1), "r"(a2), "r"(a3), "r"(b0), "r"(b1));
}

// ================= tf32 GEMM: C[M,N] = A[M,K] @ B[N,K]^T + bias ==========
// BM=128, BN=128, BK=16, 256 threads (8 warps as 2x4), warp tile 64x32.
#define GM_BM 128
#define GM_BN 128
#define GM_BK 16
#define GSTR  20   // smem row stride (16 + 4): frag loads conflict-free

__device__ __forceinline__ void gemm_tile_tf32(
    const float* __restrict__ A, const float* __restrict__ B,
    const float* __restrict__ bias, float* __restrict__ C,
    int M, int N, int K, int m0, int n0,
    uint32_t* As, uint32_t* Bs)
{
    const int tid = threadIdx.x;
    const int lane = tid & 31;
    const int wid = tid >> 5;
    const int wm = wid >> 2;       // 0..1
    const int wn = wid & 3;        // 0..3

    int arow[2], brow[2], akc[2];
#pragma unroll
    for (int i = 0; i < 2; ++i) {
        int s = tid + i * 256;
        int r = s >> 2;
        akc[i] = (s & 3) * 4;
        arow[i] = min(m0 + r, M - 1);
        brow[i] = n0 + r;
    }

    float4 areg[2], breg[2];
#pragma unroll
    for (int i = 0; i < 2; ++i) {
        areg[i] = *(const float4*)(A + (size_t)arow[i] * K + akc[i]);
        breg[i] = *(const float4*)(B + (size_t)brow[i] * K + akc[i]);
    }

    float acc[16][4];
#pragma unroll
    for (int t = 0; t < 16; ++t)
        acc[t][0] = acc[t][1] = acc[t][2] = acc[t][3] = 0.f;

    for (int k0 = 0; k0 < K; k0 += GM_BK) {
#pragma unroll
        for (int i = 0; i < 2; ++i) {
            int s = tid + i * 256;
            int r = s >> 2;
            int kc = (s & 3) * 4;
            uint32_t* pa = &As[r * GSTR + kc];
            pa[0] = f2tf(areg[i].x); pa[1] = f2tf(areg[i].y);
            pa[2] = f2tf(areg[i].z); pa[3] = f2tf(areg[i].w);
            uint32_t* pb = &Bs[r * GSTR + kc];
            pb[0] = f2tf(breg[i].x); pb[1] = f2tf(breg[i].y);
            pb[2] = f2tf(breg[i].z); pb[3] = f2tf(breg[i].w);
        }
        __syncthreads();

        if (k0 + GM_BK < K) {
#pragma unroll
            for (int i = 0; i < 2; ++i) {
                areg[i] = *(const float4*)(A + (size_t)arow[i] * K + k0 + GM_BK + akc[i]);
                breg[i] = *(const float4*)(B + (size_t)brow[i] * K + k0 + GM_BK + akc[i]);
            }
        }

#pragma unroll
        for (int ks = 0; ks < 2; ++ks) {
            const int kb = ks * 8;
            uint32_t af[4][4], bf[4][2];
#pragma unroll
            for (int mt = 0; mt < 4; ++mt) {
                int r = wm * 64 + mt * 16 + (lane >> 2);
                af[mt][0] = As[r * GSTR + kb + (lane & 3)];
                af[mt][1] = As[(r + 8) * GSTR + kb + (lane & 3)];
                af[mt][2] = As[r * GSTR + kb + (lane & 3) + 4];
                af[mt][3] = As[(r + 8) * GSTR + kb + (lane & 3) + 4];
            }
#pragma unroll
            for (int nt = 0; nt < 4; ++nt) {
                int r = wn * 32 + nt * 8 + (lane >> 2);
                bf[nt][0] = Bs[r * GSTR + kb + (lane & 3)];
                bf[nt][1] = Bs[r * GSTR + kb + (lane & 3) + 4];
            }
#pragma unroll
            for (int mt = 0; mt < 4; ++mt)
#pragma unroll
                for (int nt = 0; nt < 4; ++nt)
                    mma_tf32(acc[mt * 4 + nt],
                             af[mt][0], af[mt][1], af[mt][2], af[mt][3],
                             bf[nt][0], bf[nt][1]);
        }
        __syncthreads();
    }

    // epilogue
#pragma unroll
    for (int mt = 0; mt < 4; ++mt) {
        int r = m0 + wm * 64 + mt * 16 + (lane >> 2);
#pragma unroll
        for (int nt = 0; nt < 4; ++nt) {
            int c = n0 + wn * 32 + nt * 8 + (lane & 3) * 2;
            float b0 = bias[c], b1 = bias[c + 1];
            float* a4 = acc[mt * 4 + nt];
            if (r < M)
                *(float2*)(C + (size_t)r * N + c) = make_float2(a4[0] + b0, a4[1] + b1);
            if (r + 8 < M)
                *(float2*)(C + (size_t)(r + 8) * N + c) = make_float2(a4[2] + b0, a4[3] + b1);
        }
    }
}

__global__ void __launch_bounds__(256) qkv_gemm_tf32(
    const float* __restrict__ x,
    const float* __restrict__ Wq, const float* __restrict__ bq,
    const float* __restrict__ Wk, const float* __restrict__ bk,
    const float* __restrict__ Wv, const float* __restrict__ bv)
{
    __shared__ uint32_t As[GM_BM * GSTR];
    __shared__ uint32_t Bs[GM_BN * GSTR];
    const float* W; const float* b; float* out;
    if (blockIdx.z == 0)      { W = Wq; b = bq; out = g_q; }
    else if (blockIdx.z == 1) { W = Wk; b = bk; out = g_k; }
    else                      { W = Wv; b = bv; out = g_v; }
    gemm_tile_tf32(x, W, b, out, LTOK, DIM, DIM,
                   blockIdx.y * GM_BM, blockIdx.x * GM_BN, As, Bs);
}

__global__ void __launch_bounds__(256) out_gemm_tf32(
    const float* __restrict__ Wo, const float* __restrict__ bo,
    float* __restrict__ out)
{
    __shared__ uint32_t As[GM_BM * GSTR];
    __shared__ uint32_t Bs[GM_BN * GSTR];
    gemm_tile_tf32(g_o, Wo, bo, out, LTOK, DIM, DIM,
                   blockIdx.y * GM_BM, blockIdx.x * GM_BN, As, Bs);
}

// ================= fused RMSNorm + RoPE (q and k) =================
__global__ void __launch_bounds__(256) rmsnorm_rope(
    const float* __restrict__ gq, const float* __restrict__ gk,
    const float* __restrict__ freqs, const int* __restrict__ gsz)
{
    const int t = blockIdx.x;
    const int which = blockIdx.y;
    float* row = (which ? g_k : g_q) + (size_t)t * DIM;
    const float* g = which ? gk : gq;
    const int tid = threadIdx.x;

    float ss = 0.f;
    for (int i = tid; i < DIM; i += 256) {
        float v = row[i];
        ss += v * v;
    }
    __shared__ float red[8];
#pragma unroll
    for (int o = 16; o; o >>= 1) ss += __shfl_xor_sync(0xffffffffu, ss, o);
    if ((tid & 31) == 0) red[tid >> 5] = ss;
    __syncthreads();
    if (tid < 8) {
        float v = red[tid];
#pragma unroll
        for (int o = 4; o; o >>= 1) v += __shfl_xor_sync(0xffu, v, o);
        if (tid == 0) red[0] = v;
    }
    __syncthreads();
    const float rms = rsqrtf(red[0] * (1.0f / DIM) + EPS);

    const int Hs = gsz[1], Ws = gsz[2];
    const int fi = t / (Hs * Ws);
    const int hi = (t / Ws) % Hs;
    const int wi = t % Ws;

    for (int p = tid; p < HEADS * 64; p += 256) {
        const int h = p >> 6;
        const int j = p & 63;
        const int pos = (j < 22) ? fi : ((j < 43) ? hi : wi);
        const float ang = freqs[pos * 64 + j];
        float c, s;
        sincosf(ang, &s, &c);
        const int d0 = h * HD + 2 * j;
        const float x0 = row[d0]     * rms * g[d0];
        const float x1 = row[d0 + 1] * rms * g[d0 + 1];
        row[d0]     = x0 * c - x1 * s;
        row[d0 + 1] = x0 * s + x1 * c;
    }
}

// ================= flash attention (tf32 mma) =================
#define FQ 64
#define FK 64
#define QST 132     // 132 % 32 = 4  -> bank = 4m+k conflict-free frags
#define KST 132
#define VST 136     // 136 % 32 = 8  -> bank = 8k+n conflict-free frags
#define SST 68      // 68  % 32 = 4
#define FLASH_SMEM_FLOATS (FQ * QST + FK * VST + FQ * SST + 3 * FQ)

__global__ void __launch_bounds__(256) flash_tf32()
{
    extern __shared__ float sm[];
    float* Qs  = sm;
    float* KVs = Qs + FQ * QST;
    float* Ss  = KVs + FK * VST;
    float* m_s = Ss + FQ * SST;
    float* l_s = m_s + FQ;
    float* f_s = l_s + FQ;
    uint32_t* Qu  = (uint32_t*)Qs;
    uint32_t* KVu = (uint32_t*)KVs;
    uint32_t* Su  = (uint32_t*)Ss;

    const int tid = threadIdx.x;
    const int lane = tid & 31;
    const int wid = tid >> 5;
    const int wm = wid >> 2;   // 0..1  (q half)
    const int wn = wid & 3;    // 0..3
    const int h  = blockIdx.y;
    const int q0 = blockIdx.x * FQ;

    // load Q tile, scale, convert to tf32
    for (int i = tid; i < FQ * 32; i += 256) {
        int r = i >> 5, c4 = (i & 31) * 4;
        float4 v = *(const float4*)(g_q + (size_t)(q0 + r) * DIM + h * HD + c4);
        uint32_t* p = &Qu[r * QST + c4];
        p[0] = f2tf(v.x * SCALE); p[1] = f2tf(v.y * SCALE);
        p[2] = f2tf(v.z * SCALE); p[3] = f2tf(v.w * SCALE);
    }
    if (tid < FQ) { m_s[tid] = -3.0e38f; l_s[tid] = 0.f; }

    float O[8][4];    // [mt*4+nt][4]
#pragma unroll
    for (int t = 0; t < 8; ++t) O[t][0] = O[t][1] = O[t][2] = O[t][3] = 0.f;

    for (int t0 = 0; t0 < LTOK; t0 += FK) {
        __syncthreads();
        // load K tile
        for (int i = tid; i < FK * 32; i += 256) {
            int r = i >> 5, c4 = (i & 31) * 4;
            float4 v = *(const float4*)(g_k + (size_t)(t0 + r) * DIM + h * HD + c4);
            uint32_t* p = &KVu[r * KST + c4];
            p[0] = f2tf(v.x); p[1] = f2tf(v.y); p[2] = f2tf(v.z); p[3] = f2tf(v.w);
        }
        __syncthreads();

        // S = Q K^T : warp tile 32(q) x 16(kv)
        float Sacc[2][2][4] = {};
#pragma unroll
        for (int ks = 0; ks < 16; ++ks) {
            const int kb = ks * 8;
            uint32_t af[2][4], bf[2][2];
#pragma unroll
            for (int mt = 0; mt < 2; ++mt) {
                int r = wm * 32 + mt * 16 + (lane >> 2);
                af[mt][0] = Qu[r * QST + kb + (lane & 3)];
                af[mt][1] = Qu[(r + 8) * QST + kb + (lane & 3)];
                af[mt][2] = Qu[r * QST + kb + (lane & 3) + 4];
                af[mt][3] = Qu[(r + 8) * QST + kb + (lane & 3) + 4];
            }
#pragma unroll
            for (int nt = 0; nt < 2; ++nt) {
                int r = wn * 16 + nt * 8 + (lane >> 2);
                bf[nt][0] = KVu[r * KST + kb + (lane & 3)];
                bf[nt][1] = KVu[r * KST + kb + (lane & 3) + 4];
            }
#pragma unroll
            for (int mt = 0; mt < 2; ++mt)
#pragma unroll
                for (int nt = 0; nt < 2; ++nt)
                    mma_tf32(Sacc[mt][nt],
                             af[mt][0], af[mt][1], af[mt][2], af[mt][3],
                             bf[nt][0], bf[nt][1]);
        }
#pragma unroll
        for (int mt = 0; mt < 2; ++mt) {
            int r = wm * 32 + mt * 16 + (lane >> 2);
#pragma unroll
            for (int nt = 0; nt < 2; ++nt) {
                int c = wn * 16 + nt * 8 + (lane & 3) * 2;
                *(float2*)&Ss[r * SST + c] = make_float2(Sacc[mt][nt][0], Sacc[mt][nt][1]);
                *(float2*)&Ss[(r + 8) * SST + c] = make_float2(Sacc[mt][nt][2], Sacc[mt][nt][3]);
            }
        }
        __syncthreads();

        // load V into KVs (stride VST) + online softmax on Ss
        for (int i = tid; i < FK * 32; i += 256) {
            int r = i >> 5, c4 = (i & 31) * 4;
            float4 v = *(const float4*)(g_v + (size_t)(t0 + r) * DIM + h * HD + c4);
            uint32_t* p = &KVu[r * VST + c4];
            p[0] = f2tf(v.x); p[1] = f2tf(v.y); p[2] = f2tf(v.z); p[3] = f2tf(v.w);
        }
        {
            const int row = tid >> 2;
            const int seg = tid & 3;
            const float mold = m_s[row];
            float vals[16];
            float tm = -3.0e38f;
#pragma unroll
            for (int c = 0; c < 16; ++c) {
                vals[c] = Ss[row * SST + seg * 16 + c];
                tm = fmaxf(tm, vals[c]);
            }
            tm = fmaxf(tm, __shfl_xor_sync(0xffffffffu, tm, 1));
            tm = fmaxf(tm, __shfl_xor_sync(0xffffffffu, tm, 2));
            const float mnew = fmaxf(mold, tm);
            float psum = 0.f;
#pragma unroll
            for (int c = 0; c < 16; ++c) {
                float p = __expf(vals[c] - mnew);
                psum += p;
                Su[row * SST + seg * 16 + c] = f2tf(p);
            }
            psum += __shfl_xor_sync(0xffffffffu, psum, 1);
            psum += __shfl_xor_sync(0xffffffffu, psum, 2);
            if (seg == 0) {
                float f = __expf(mold - mnew);
                f_s[row] = f;
                l_s[row] = l_s[row] * f + psum;
                m_s[row] = mnew;
            }
        }
        __syncthreads();

        // O = O*f + P @ V : warp tile 32(q) x 32(hd)
#pragma unroll
        for (int mt = 0; mt < 2; ++mt) {
            int r = wm * 32 + mt * 16 + (lane >> 2);
            float f0 = f_s[r], f1 = f_s[r + 8];
#pragma unroll
            for (int nt = 0; nt < 4; ++nt) {
                O[mt * 4 + nt][0] *= f0; O[mt * 4 + nt][1] *= f0;
                O[mt * 4 + nt][2] *= f1; O[mt * 4 + nt][3] *= f1;
            }
        }
#pragma unroll
        for (int ks = 0; ks < 8; ++ks) {
            const int kb = ks * 8;
            uint32_t af[2][4], bf[4][2];
#pragma unroll
            for (int mt = 0; mt < 2; ++mt) {
                int r = wm * 32 + mt * 16 + (lane >> 2);
                af[mt][0] = Su[r * SST + kb + (lane & 3)];
                af[mt][1] = Su[(r + 8) * SST + kb + (lane & 3)];
                af[mt][2] = Su[r * SST + kb + (lane & 3) + 4];
                af[mt][3] = Su[(r + 8) * SST + kb + (lane & 3) + 4];
            }
#pragma unroll
            for (int nt = 0; nt < 4; ++nt) {
                int c = wn * 32 + nt * 8 + (lane >> 2);
                bf[nt][0] = KVu[(kb + (lane & 3)) * VST + c];
                bf[nt][1] = KVu[(kb + (lane & 3) + 4) * VST + c];
            }
#pragma unroll
            for (int mt = 0; mt < 2; ++mt)
#pragma unroll
                for (int nt = 0; nt < 4; ++nt)
                    mma_tf32(O[mt * 4 + nt],
                             af[mt][0], af[mt][1], af[mt][2], af[mt][3],
                             bf[nt][0], bf[nt][1]);
        }
    }

    // finalize
#pragma unroll
    for (int mt = 0; mt < 2; ++mt) {
        int r = wm * 32 + mt * 16 + (lane >> 2);
        float inv0 = 1.f / l_s[r], inv1 = 1.f / l_s[r + 8];
#pragma unroll
        for (int nt = 0; nt < 4; ++nt) {
            int c = wn * 32 + nt * 8 + (lane & 3) * 2;
            float* d0 = g_o + (size_t)(q0 + r) * DIM + h * HD + c;
            *(float2*)d0 = make_float2(O[mt * 4 + nt][0] * inv0, O[mt * 4 + nt][1] * inv0);
            float* d1 = g_o + (size_t)(q0 + r + 8) * DIM + h * HD + c;
            *(float2*)d1 = make_float2(O[mt * 4 + nt][2] * inv1, O[mt * 4 + nt][3] * inv1);
        }
    }
}

// ================= launch =================
extern "C" void kernel_launch(void* const* d_in, const int* in_sizes, int n_in,
                              void* d_out, int out_size)
{
    const float* x          = (const float*)d_in[0];
    const int*   grid_sizes = (const int*)d_in[2];
    const float* freqs      = (const float*)d_in[3];
    const float* Wq = (const float*)d_in[4];
    const float* bq = (const float*)d_in[5];
    const float* Wk = (const float*)d_in[6];
    const float* bk = (const float*)d_in[7];
    const float* Wv = (const float*)d_in[8];
    const float* bv = (const float*)d_in[9];
    const float* Wo = (const float*)d_in[10];
    const float* bo = (const float*)d_in[11];
    const float* gq = (const float*)d_in[12];
    const float* gk = (const float*)d_in[13];
    float* out = (float*)d_out;

    const int flash_smem = FLASH_SMEM_FLOATS * sizeof(float);
    cudaFuncSetAttribute(flash_tf32, cudaFuncAttributeMaxDynamicSharedMemorySize, flash_smem);

    const int gmy = (LTOK + GM_BM - 1) / GM_BM;   // 28
    dim3 gqkv(DIM / GM_BN, gmy, 3);

    qkv_gemm_tf32<<<gqkv, 256>>>(x, Wq, bq, Wk, bk, Wv, bv);
    rmsnorm_rope<<<dim3(LTOK, 2), 256>>>(gq, gk, freqs, grid_sizes);
    flash_tf32<<<dim3(LTOK / FQ, HEADS), 256, flash_smem>>>();
    out_gemm_tf32<<<dim3(DIM / GM_BN, gmy), 256>>>(Wo, bo, out);
}

// round 3
// speedup vs baseline: 4.1446x; 1.0337x over previous
#include <cuda_runtime.h>
#include <cstdint>

#define DIM    1536
#define HEADS  12
#define HD     128
#define LTOK   3520
#define EPS    1e-6f
#define SCALE  0.08838834764831845f   // 1/sqrt(128)

// ---------------- scratch (no allocation allowed) ----------------
__device__ float g_q[LTOK * DIM];
__device__ float g_k[LTOK * DIM];
__device__ float g_v[LTOK * DIM];
__device__ float g_o[LTOK * DIM];

// ---------------- tf32 helpers ----------------
__device__ __forceinline__ uint32_t f2tf(float f) {
    uint32_t u;
    asm("cvt.rna.tf32.f32 %0, %1;" : "=r"(u) : "f"(f));
    return u;
}

__device__ __forceinline__ void mma_tf32(float c[4],
    uint32_t a0, uint32_t a1, uint32_t a2, uint32_t a3,
    uint32_t b0, uint32_t b1)
{
    asm volatile(
        "mma.sync.aligned.m16n8k8.row.col.f32.tf32.tf32.f32 "
        "{%0,%1,%2,%3}, {%4,%5,%6,%7}, {%8,%9}, {%0,%1,%2,%3};\n"
        : "+f"(c[0]), "+f"(c[1]), "+f"(c[2]), "+f"(c[3])
        : "r"(a0), "r"(a1), "r"(a2), "r"(a3), "r"(b0), "r"(b1));
}

// ================= tf32 GEMM: C[M,N] = A[M,K] @ B[N,K]^T + bias ==========
// BM=128, BN=128, BK=16, 256 threads (8 warps as 2x4), warp tile 64x32.
// 2-stage smem double buffer, 1 syncthreads per K-iter.
#define GM_BM 128
#define GM_BN 128
#define GM_BK 16
#define GSTR  20   // smem row stride (16 + 4): frag loads conflict-free
#define GM_STAGE (GM_BM * GSTR)

__device__ __forceinline__ void gemm_tile_tf32(
    const float* __restrict__ A, const float* __restrict__ B,
    const float* __restrict__ bias, float* __restrict__ C,
    int M, int N, int K, int m0, int n0,
    uint32_t* As, uint32_t* Bs)   // each holds 2 stages
{
    const int tid = threadIdx.x;
    const int lane = tid & 31;
    const int wid = tid >> 5;
    const int wm = wid >> 2;       // 0..1
    const int wn = wid & 3;        // 0..3

    int arow[2], brow[2], akc[2], srow[2];
#pragma unroll
    for (int i = 0; i < 2; ++i) {
        int s = tid + i * 256;
        srow[i] = s >> 2;
        akc[i] = (s & 3) * 4;
        arow[i] = min(m0 + srow[i], M - 1);
        brow[i] = n0 + srow[i];
    }

    float4 areg[2], breg[2];
#pragma unroll
    for (int i = 0; i < 2; ++i) {
        areg[i] = *(const float4*)(A + (size_t)arow[i] * K + akc[i]);
        breg[i] = *(const float4*)(B + (size_t)brow[i] * K + akc[i]);
    }
    // store stage 0
#pragma unroll
    for (int i = 0; i < 2; ++i) {
        uint32_t* pa = &As[srow[i] * GSTR + akc[i]];
        pa[0] = f2tf(areg[i].x); pa[1] = f2tf(areg[i].y);
        pa[2] = f2tf(areg[i].z); pa[3] = f2tf(areg[i].w);
        uint32_t* pb = &Bs[srow[i] * GSTR + akc[i]];
        pb[0] = f2tf(breg[i].x); pb[1] = f2tf(breg[i].y);
        pb[2] = f2tf(breg[i].z); pb[3] = f2tf(breg[i].w);
    }
    __syncthreads();

    float acc[16][4];
#pragma unroll
    for (int t = 0; t < 16; ++t)
        acc[t][0] = acc[t][1] = acc[t][2] = acc[t][3] = 0.f;

    int buf = 0;
    for (int k0 = 0; k0 < K; k0 += GM_BK) {
        const bool has_next = (k0 + GM_BK < K);
        if (has_next) {
#pragma unroll
            for (int i = 0; i < 2; ++i) {
                areg[i] = *(const float4*)(A + (size_t)arow[i] * K + k0 + GM_BK + akc[i]);
                breg[i] = *(const float4*)(B + (size_t)brow[i] * K + k0 + GM_BK + akc[i]);
            }
        }

        const uint32_t* Ab = As + buf * GM_STAGE;
        const uint32_t* Bb = Bs + buf * GM_STAGE;
#pragma unroll
        for (int ks = 0; ks < 2; ++ks) {
            const int kb = ks * 8;
            uint32_t af[4][4], bf[4][2];
#pragma unroll
            for (int mt = 0; mt < 4; ++mt) {
                int r = wm * 64 + mt * 16 + (lane >> 2);
                af[mt][0] = Ab[r * GSTR + kb + (lane & 3)];
                af[mt][1] = Ab[(r + 8) * GSTR + kb + (lane & 3)];
                af[mt][2] = Ab[r * GSTR + kb + (lane & 3) + 4];
                af[mt][3] = Ab[(r + 8) * GSTR + kb + (lane & 3) + 4];
            }
#pragma unroll
            for (int nt = 0; nt < 4; ++nt) {
                int r = wn * 32 + nt * 8 + (lane >> 2);
                bf[nt][0] = Bb[r * GSTR + kb + (lane & 3)];
                bf[nt][1] = Bb[r * GSTR + kb + (lane & 3) + 4];
            }
#pragma unroll
            for (int mt = 0; mt < 4; ++mt)
#pragma unroll
                for (int nt = 0; nt < 4; ++nt)
                    mma_tf32(acc[mt * 4 + nt],
                             af[mt][0], af[mt][1], af[mt][2], af[mt][3],
                             bf[nt][0], bf[nt][1]);
        }

        if (has_next) {
            uint32_t* An = As + (buf ^ 1) * GM_STAGE;
            uint32_t* Bn = Bs + (buf ^ 1) * GM_STAGE;
#pragma unroll
            for (int i = 0; i < 2; ++i) {
                uint32_t* pa = &An[srow[i] * GSTR + akc[i]];
                pa[0] = f2tf(areg[i].x); pa[1] = f2tf(areg[i].y);
                pa[2] = f2tf(areg[i].z); pa[3] = f2tf(areg[i].w);
                uint32_t* pb = &Bn[srow[i] * GSTR + akc[i]];
                pb[0] = f2tf(breg[i].x); pb[1] = f2tf(breg[i].y);
                pb[2] = f2tf(breg[i].z); pb[3] = f2tf(breg[i].w);
            }
        }
        __syncthreads();
        buf ^= 1;
    }

    // epilogue
#pragma unroll
    for (int nt = 0; nt < 4; ++nt) {
        int c = n0 + wn * 32 + nt * 8 + (lane & 3) * 2;
        float b0 = bias[c], b1 = bias[c + 1];
#pragma unroll
        for (int mt = 0; mt < 4; ++mt) {
            int r = m0 + wm * 64 + mt * 16 + (lane >> 2);
            float* a4 = acc[mt * 4 + nt];
            if (r < M)
                *(float2*)(C + (size_t)r * N + c) = make_float2(a4[0] + b0, a4[1] + b1);
            if (r + 8 < M)
                *(float2*)(C + (size_t)(r + 8) * N + c) = make_float2(a4[2] + b0, a4[3] + b1);
        }
    }
}

__global__ void __launch_bounds__(256, 2) qkv_gemm_tf32(
    const float* __restrict__ x,
    const float* __restrict__ Wq, const float* __restrict__ bq,
    const float* __restrict__ Wk, const float* __restrict__ bk,
    const float* __restrict__ Wv, const float* __restrict__ bv)
{
    __shared__ uint32_t As[2 * GM_STAGE];
    __shared__ uint32_t Bs[2 * GM_STAGE];
    const float* W; const float* b; float* out;
    if (blockIdx.z == 0)      { W = Wq; b = bq; out = g_q; }
    else if (blockIdx.z == 1) { W = Wk; b = bk; out = g_k; }
    else                      { W = Wv; b = bv; out = g_v; }
    gemm_tile_tf32(x, W, b, out, LTOK, DIM, DIM,
                   blockIdx.y * GM_BM, blockIdx.x * GM_BN, As, Bs);
}

__global__ void __launch_bounds__(256, 2) out_gemm_tf32(
    const float* __restrict__ Wo, const float* __restrict__ bo,
    float* __restrict__ out)
{
    __shared__ uint32_t As[2 * GM_STAGE];
    __shared__ uint32_t Bs[2 * GM_STAGE];
    gemm_tile_tf32(g_o, Wo, bo, out, LTOK, DIM, DIM,
                   blockIdx.y * GM_BM, blockIdx.x * GM_BN, As, Bs);
}

// ================= fused RMSNorm + RoPE (q and k) =================
__global__ void __launch_bounds__(256) rmsnorm_rope(
    const float* __restrict__ gq, const float* __restrict__ gk,
    const float* __restrict__ freqs, const int* __restrict__ gsz)
{
    const int t = blockIdx.x;
    const int which = blockIdx.y;
    float* row = (which ? g_k : g_q) + (size_t)t * DIM;
    const float* g = which ? gk : gq;
    const int tid = threadIdx.x;

    float ss = 0.f;
    for (int i = tid; i < DIM; i += 256) {
        float v = row[i];
        ss += v * v;
    }
    __shared__ float red[8];
#pragma unroll
    for (int o = 16; o; o >>= 1) ss += __shfl_xor_sync(0xffffffffu, ss, o);
    if ((tid & 31) == 0) red[tid >> 5] = ss;
    __syncthreads();
    if (tid < 8) {
        float v = red[tid];
#pragma unroll
        for (int o = 4; o; o >>= 1) v += __shfl_xor_sync(0xffu, v, o);
        if (tid == 0) red[0] = v;
    }
    __syncthreads();
    const float rms = rsqrtf(red[0] * (1.0f / DIM) + EPS);

    const int Hs = gsz[1], Ws = gsz[2];
    const int fi = t / (Hs * Ws);
    const int hi = (t / Ws) % Hs;
    const int wi = t % Ws;

    for (int p = tid; p < HEADS * 64; p += 256) {
        const int h = p >> 6;
        const int j = p & 63;
        const int pos = (j < 22) ? fi : ((j < 43) ? hi : wi);
        const float ang = freqs[pos * 64 + j];
        float c, s;
        sincosf(ang, &s, &c);
        const int d0 = h * HD + 2 * j;
        const float x0 = row[d0]     * rms * g[d0];
        const float x1 = row[d0 + 1] * rms * g[d0 + 1];
        row[d0]     = x0 * c - x1 * s;
        row[d0 + 1] = x0 * s + x1 * c;
    }
}

// ================= flash attention (tf32 mma, reg-staged K/V prefetch) ====
#define FQ 64
#define FK 64
#define QST 132     // % 32 = 4  -> conflict-free frag loads
#define KVST 132
#define SST 68      // % 32 = 4
#define FLASH_SMEM_FLOATS (FQ * QST + FK * KVST + FQ * SST + 3 * FQ)

__global__ void __launch_bounds__(256, 2) flash_tf32()
{
    extern __shared__ float sm[];
    float* Qs  = sm;
    float* KVs = Qs + FQ * QST;
    float* Ss  = KVs + FK * KVST;
    float* m_s = Ss + FQ * SST;
    float* l_s = m_s + FQ;
    float* f_s = l_s + FQ;
    uint32_t* Qu  = (uint32_t*)Qs;
    uint32_t* KVu = (uint32_t*)KVs;
    uint32_t* Su  = (uint32_t*)Ss;

    const int tid = threadIdx.x;
    const int lane = tid & 31;
    const int wid = tid >> 5;
    const int wm = wid >> 2;   // 0..1  (q half)
    const int wn = wid & 3;    // 0..3
    const int h  = blockIdx.y;
    const int q0 = blockIdx.x * FQ;

    // per-thread staging indices (8 float4 per tile)
    int srow[8], scol[8];
#pragma unroll
    for (int j = 0; j < 8; ++j) {
        int i = tid + j * 256;
        srow[j] = i >> 5;
        scol[j] = (i & 31) * 4;
    }

    // load Q tile, scale, convert to tf32
#pragma unroll
    for (int j = 0; j < 8; ++j) {
        float4 v = *(const float4*)(g_q + (size_t)(q0 + srow[j]) * DIM + h * HD + scol[j]);
        uint32_t* p = &Qu[srow[j] * QST + scol[j]];
        p[0] = f2tf(v.x * SCALE); p[1] = f2tf(v.y * SCALE);
        p[2] = f2tf(v.z * SCALE); p[3] = f2tf(v.w * SCALE);
    }
    if (tid < FQ) { m_s[tid] = -3.0e38f; l_s[tid] = 0.f; }

    float O[8][4];
#pragma unroll
    for (int t = 0; t < 8; ++t) O[t][0] = O[t][1] = O[t][2] = O[t][3] = 0.f;

    // prefetch K(0) into registers
    float4 kreg[8];
#pragma unroll
    for (int j = 0; j < 8; ++j)
        kreg[j] = *(const float4*)(g_k + (size_t)srow[j] * DIM + h * HD + scol[j]);

    for (int t0 = 0; t0 < LTOK; t0 += FK) {
        __syncthreads();   // (1) prev PV reads of KVs done
        // commit K(t) registers -> smem
#pragma unroll
        for (int j = 0; j < 8; ++j) {
            uint32_t* p = &KVu[srow[j] * KVST + scol[j]];
            p[0] = f2tf(kreg[j].x); p[1] = f2tf(kreg[j].y);
            p[2] = f2tf(kreg[j].z); p[3] = f2tf(kreg[j].w);
        }
        __syncthreads();   // (2) K visible

        // issue V(t) loads early (latency hidden behind S-phase MMAs)
        float4 vreg[8];
#pragma unroll
        for (int j = 0; j < 8; ++j)
            vreg[j] = *(const float4*)(g_v + (size_t)(t0 + srow[j]) * DIM + h * HD + scol[j]);

        // S = Q K^T : warp tile 32(q) x 16(kv)
        float Sacc[2][2][4] = {};
#pragma unroll
        for (int ks = 0; ks < 16; ++ks) {
            const int kb = ks * 8;
            uint32_t af[2][4], bf[2][2];
#pragma unroll
            for (int mt = 0; mt < 2; ++mt) {
                int r = wm * 32 + mt * 16 + (lane >> 2);
                af[mt][0] = Qu[r * QST + kb + (lane & 3)];
                af[mt][1] = Qu[(r + 8) * QST + kb + (lane & 3)];
                af[mt][2] = Qu[r * QST + kb + (lane & 3) + 4];
                af[mt][3] = Qu[(r + 8) * QST + kb + (lane & 3) + 4];
            }
#pragma unroll
            for (int nt = 0; nt < 2; ++nt) {
                int r = wn * 16 + nt * 8 + (lane >> 2);
                bf[nt][0] = KVu[r * KVST + kb + (lane & 3)];
                bf[nt][1] = KVu[r * KVST + kb + (lane & 3) + 4];
            }
#pragma unroll
            for (int mt = 0; mt < 2; ++mt)
#pragma unroll
                for (int nt = 0; nt < 2; ++nt)
                    mma_tf32(Sacc[mt][nt],
                             af[mt][0], af[mt][1], af[mt][2], af[mt][3],
                             bf[nt][0], bf[nt][1]);
        }
#pragma unroll
        for (int mt = 0; mt < 2; ++mt) {
            int r = wm * 32 + mt * 16 + (lane >> 2);
#pragma unroll
            for (int nt = 0; nt < 2; ++nt) {
                int c = wn * 16 + nt * 8 + (lane & 3) * 2;
                *(float2*)&Ss[r * SST + c] = make_float2(Sacc[mt][nt][0], Sacc[mt][nt][1]);
                *(float2*)&Ss[(r + 8) * SST + c] = make_float2(Sacc[mt][nt][2], Sacc[mt][nt][3]);
            }
        }

        // prefetch K(t+1) into registers (consumed after next sync (1))
        if (t0 + FK < LTOK) {
#pragma unroll
            for (int j = 0; j < 8; ++j)
                kreg[j] = *(const float4*)(g_k + (size_t)(t0 + FK + srow[j]) * DIM + h * HD + scol[j]);
        }
        __syncthreads();   // (3) Ss visible, KVs free

        // commit V registers -> smem (loads long since landed)
#pragma unroll
        for (int j = 0; j < 8; ++j) {
            uint32_t* p = &KVu[srow[j] * KVST + scol[j]];
            p[0] = f2tf(vreg[j].x); p[1] = f2tf(vreg[j].y);
            p[2] = f2tf(vreg[j].z); p[3] = f2tf(vreg[j].w);
        }

        // online softmax on Ss
        {
            const int row = tid >> 2;
            const int seg = tid & 3;
            const float mold = m_s[row];
            float vals[16];
            float tm = -3.0e38f;
#pragma unroll
            for (int c = 0; c < 16; ++c) {
                vals[c] = Ss[row * SST + seg * 16 + c];
                tm = fmaxf(tm, vals[c]);
            }
            tm = fmaxf(tm, __shfl_xor_sync(0xffffffffu, tm, 1));
            tm = fmaxf(tm, __shfl_xor_sync(0xffffffffu, tm, 2));
            const float mnew = fmaxf(mold, tm);
            float psum = 0.f;
#pragma unroll
            for (int c = 0; c < 16; ++c) {
                float p = __expf(vals[c] - mnew);
                psum += p;
                Su[row * SST + seg * 16 + c] = f2tf(p);
            }
            psum += __shfl_xor_sync(0xffffffffu, psum, 1);
            psum += __shfl_xor_sync(0xffffffffu, psum, 2);
            if (seg == 0) {
                float f = __expf(mold - mnew);
                f_s[row] = f;
                l_s[row] = l_s[row] * f + psum;
                m_s[row] = mnew;
            }
        }
        __syncthreads();   // (4) V + Su + f_s visible

        // O = O*f + P @ V : warp tile 32(q) x 32(hd)
#pragma unroll
        for (int mt = 0; mt < 2; ++mt) {
            int r = wm * 32 + mt * 16 + (lane >> 2);
            float f0 = f_s[r], f1 = f_s[r + 8];
#pragma unroll
            for (int nt = 0; nt < 4; ++nt) {
                O[mt * 4 + nt][0] *= f0; O[mt * 4 + nt][1] *= f0;
                O[mt * 4 + nt][2] *= f1; O[mt * 4 + nt][3] *= f1;
            }
        }
#pragma unroll
        for (int ks = 0; ks < 8; ++ks) {
            const int kb = ks * 8;
            uint32_t af[2][4], bf[4][2];
#pragma unroll
            for (int mt = 0; mt < 2; ++mt) {
                int r = wm * 32 + mt * 16 + (lane >> 2);
                af[mt][0] = Su[r * SST + kb + (lane & 3)];
                af[mt][1] = Su[(r + 8) * SST + kb + (lane & 3)];
                af[mt][2] = Su[r * SST + kb + (lane & 3) + 4];
                af[mt][3] = Su[(r + 8) * SST + kb + (lane & 3) + 4];
            }
#pragma unroll
            for (int nt = 0; nt < 4; ++nt) {
                int c = wn * 32 + nt * 8 + (lane >> 2);
                bf[nt][0] = KVu[(kb + (lane & 3)) * KVST + c];
                bf[nt][1] = KVu[(kb + (lane & 3) + 4) * KVST + c];
            }
#pragma unroll
            for (int mt = 0; mt < 2; ++mt)
#pragma unroll
                for (int nt = 0; nt < 4; ++nt)
                    mma_tf32(O[mt * 4 + nt],
                             af[mt][0], af[mt][1], af[mt][2], af[mt][3],
                             bf[nt][0], bf[nt][1]);
        }
    }

    // finalize
#pragma unroll
    for (int mt = 0; mt < 2; ++mt) {
        int r = wm * 32 + mt * 16 + (lane >> 2);
        float inv0 = 1.f / l_s[r], inv1 = 1.f / l_s[r + 8];
#pragma unroll
        for (int nt = 0; nt < 4; ++nt) {
            int c = wn * 32 + nt * 8 + (lane & 3) * 2;
            float* d0 = g_o + (size_t)(q0 + r) * DIM + h * HD + c;
            *(float2*)d0 = make_float2(O[mt * 4 + nt][0] * inv0, O[mt * 4 + nt][1] * inv0);
            float* d1 = g_o + (size_t)(q0 + r + 8) * DIM + h * HD + c;
            *(float2*)d1 = make_float2(O[mt * 4 + nt][2] * inv1, O[mt * 4 + nt][3] * inv1);
        }
    }
}

// ================= launch =================
extern "C" void kernel_launch(void* const* d_in, const int* in_sizes, int n_in,
                              void* d_out, int out_size)
{
    const float* x          = (const float*)d_in[0];
    const int*   grid_sizes = (const int*)d_in[2];
    const float* freqs      = (const float*)d_in[3];
    const float* Wq = (const float*)d_in[4];
    const float* bq = (const float*)d_in[5];
    const float* Wk = (const float*)d_in[6];
    const float* bk = (const float*)d_in[7];
    const float* Wv = (const float*)d_in[8];
    const float* bv = (const float*)d_in[9];
    const float* Wo = (const float*)d_in[10];
    const float* bo = (const float*)d_in[11];
    const float* gq = (const float*)d_in[12];
    const float* gk = (const float*)d_in[13];
    float* out = (float*)d_out;

    const int flash_smem = FLASH_SMEM_FLOATS * sizeof(float);
    cudaFuncSetAttribute(flash_tf32, cudaFuncAttributeMaxDynamicSharedMemorySize, flash_smem);

    const int gmy = (LTOK + GM_BM - 1) / GM_BM;   // 28
    dim3 gqkv(DIM / GM_BN, gmy, 3);

    qkv_gemm_tf32<<<gqkv, 256>>>(x, Wq, bq, Wk, bk, Wv, bv);
    rmsnorm_rope<<<dim3(LTOK, 2), 256>>>(gq, gk, freqs, grid_sizes);
    flash_tf32<<<dim3(LTOK / FQ, HEADS), 256, flash_smem>>>();
    out_gemm_tf32<<<dim3(DIM / GM_BN, gmy), 256>>>(Wo, bo, out);
}

// round 6
// speedup vs baseline: 4.2997x; 1.0374x over previous
#include <cuda_runtime.h>
#include <cstdint>

#define DIM    1536
#define HEADS  12
#define HD     128
#define LTOK   3520
#define EPS    1e-6f
#define SCALE  0.08838834764831845f   // 1/sqrt(128)

// ---------------- scratch (no allocation allowed) ----------------
__device__ float g_q[LTOK * DIM];
__device__ float g_k[LTOK * DIM];
__device__ float g_v[LTOK * DIM];
__device__ float g_o[LTOK * DIM];

// ---------------- tf32 helpers ----------------
__device__ __forceinline__ uint32_t f2tf(float f) {
    uint32_t u;
    asm("cvt.rna.tf32.f32 %0, %1;" : "=r"(u) : "f"(f));
    return u;
}

__device__ __forceinline__ void mma_tf32(float c[4],
    uint32_t a0, uint32_t a1, uint32_t a2, uint32_t a3,
    uint32_t b0, uint32_t b1)
{
    asm volatile(
        "mma.sync.aligned.m16n8k8.row.col.f32.tf32.tf32.f32 "
        "{%0,%1,%2,%3}, {%4,%5,%6,%7}, {%8,%9}, {%0,%1,%2,%3};\n"
        : "+f"(c[0]), "+f"(c[1]), "+f"(c[2]), "+f"(c[3])
        : "r"(a0), "r"(a1), "r"(a2), "r"(a3), "r"(b0), "r"(b1));
}

// ================= tf32 GEMM: C[M,N] = A[M,K] @ B[N,K]^T + bias ==========
// BN=128, BK=16, 256 threads (8 warps as 2x4). BM templated (128 or 64).
// 2-stage smem double buffer, 1 syncthreads per K-iter.
#define GM_BN 128
#define GM_BK 16
#define GSTR  20   // smem row stride (16 + 4): frag loads conflict-free

template<int BM>
__device__ __forceinline__ void gemm_tile_tf32(
    const float* __restrict__ A, const float* __restrict__ B,
    const float* __restrict__ bias, float* __restrict__ C,
    int M, int N, int K, int m0, int n0,
    uint32_t* As, uint32_t* Bs)   // each holds 2 stages
{
    constexpr int MT = BM / 32;        // m16 sub-tiles per warp (4 or 2)
    constexpr int ACH = BM / 64;       // A staging float4s per thread (2 or 1)
    constexpr int A_STAGE = BM * GSTR;
    constexpr int B_STAGE = GM_BN * GSTR;

    const int tid = threadIdx.x;
    const int lane = tid & 31;
    const int wid = tid >> 5;
    const int wm = wid >> 2;       // 0..1
    const int wn = wid & 3;        // 0..3

    int arow[ACH], akc[ACH], asr[ACH];
#pragma unroll
    for (int i = 0; i < ACH; ++i) {
        int s = tid + i * 256;
        asr[i] = s >> 2;
        akc[i] = (s & 3) * 4;
        arow[i] = min(m0 + asr[i], M - 1);
    }
    int brow[2], bkc[2], bsr[2];
#pragma unroll
    for (int i = 0; i < 2; ++i) {
        int s = tid + i * 256;
        bsr[i] = s >> 2;
        bkc[i] = (s & 3) * 4;
        brow[i] = n0 + bsr[i];
    }

    float4 areg[ACH], breg[2];
#pragma unroll
    for (int i = 0; i < ACH; ++i)
        areg[i] = *(const float4*)(A + (size_t)arow[i] * K + akc[i]);
#pragma unroll
    for (int i = 0; i < 2; ++i)
        breg[i] = *(const float4*)(B + (size_t)brow[i] * K + bkc[i]);

    // store stage 0
#pragma unroll
    for (int i = 0; i < ACH; ++i) {
        uint32_t* pa = &As[asr[i] * GSTR + akc[i]];
        pa[0] = f2tf(areg[i].x); pa[1] = f2tf(areg[i].y);
        pa[2] = f2tf(areg[i].z); pa[3] = f2tf(areg[i].w);
    }
#pragma unroll
    for (int i = 0; i < 2; ++i) {
        uint32_t* pb = &Bs[bsr[i] * GSTR + bkc[i]];
        pb[0] = f2tf(breg[i].x); pb[1] = f2tf(breg[i].y);
        pb[2] = f2tf(breg[i].z); pb[3] = f2tf(breg[i].w);
    }
    __syncthreads();

    float acc[MT * 4][4];
#pragma unroll
    for (int t = 0; t < MT * 4; ++t)
        acc[t][0] = acc[t][1] = acc[t][2] = acc[t][3] = 0.f;

    int buf = 0;
    for (int k0 = 0; k0 < K; k0 += GM_BK) {
        const bool has_next = (k0 + GM_BK < K);
        if (has_next) {
#pragma unroll
            for (int i = 0; i < ACH; ++i)
                areg[i] = *(const float4*)(A + (size_t)arow[i] * K + k0 + GM_BK + akc[i]);
#pragma unroll
            for (int i = 0; i < 2; ++i)
                breg[i] = *(const float4*)(B + (size_t)brow[i] * K + k0 + GM_BK + bkc[i]);
        }

        const uint32_t* Ab = As + buf * A_STAGE;
        const uint32_t* Bb = Bs + buf * B_STAGE;
#pragma unroll
        for (int ks = 0; ks < 2; ++ks) {
            const int kb = ks * 8;
            uint32_t af[MT][4], bf[4][2];
#pragma unroll
            for (int mt = 0; mt < MT; ++mt) {
                int r = wm * (BM / 2) + mt * 16 + (lane >> 2);
                af[mt][0] = Ab[r * GSTR + kb + (lane & 3)];
                af[mt][1] = Ab[(r + 8) * GSTR + kb + (lane & 3)];
                af[mt][2] = Ab[r * GSTR + kb + (lane & 3) + 4];
                af[mt][3] = Ab[(r + 8) * GSTR + kb + (lane & 3) + 4];
            }
#pragma unroll
            for (int nt = 0; nt < 4; ++nt) {
                int r = wn * 32 + nt * 8 + (lane >> 2);
                bf[nt][0] = Bb[r * GSTR + kb + (lane & 3)];
                bf[nt][1] = Bb[r * GSTR + kb + (lane & 3) + 4];
            }
#pragma unroll
            for (int mt = 0; mt < MT; ++mt)
#pragma unroll
                for (int nt = 0; nt < 4; ++nt)
                    mma_tf32(acc[mt * 4 + nt],
                             af[mt][0], af[mt][1], af[mt][2], af[mt][3],
                             bf[nt][0], bf[nt][1]);
        }

        if (has_next) {
            uint32_t* An = As + (buf ^ 1) * A_STAGE;
            uint32_t* Bn = Bs + (buf ^ 1) * B_STAGE;
#pragma unroll
            for (int i = 0; i < ACH; ++i) {
                uint32_t* pa = &An[asr[i] * GSTR + akc[i]];
                pa[0] = f2tf(areg[i].x); pa[1] = f2tf(areg[i].y);
                pa[2] = f2tf(areg[i].z); pa[3] = f2tf(areg[i].w);
            }
#pragma unroll
            for (int i = 0; i < 2; ++i) {
                uint32_t* pb = &Bn[bsr[i] * GSTR + bkc[i]];
                pb[0] = f2tf(breg[i].x); pb[1] = f2tf(breg[i].y);
                pb[2] = f2tf(breg[i].z); pb[3] = f2tf(breg[i].w);
            }
        }
        __syncthreads();
        buf ^= 1;
    }

    // epilogue
#pragma unroll
    for (int nt = 0; nt < 4; ++nt) {
        int c = n0 + wn * 32 + nt * 8 + (lane & 3) * 2;
        float b0 = bias[c], b1 = bias[c + 1];
#pragma unroll
        for (int mt = 0; mt < MT; ++mt) {
            int r = m0 + wm * (BM / 2) + mt * 16 + (lane >> 2);
            float* a4 = acc[mt * 4 + nt];
            if (r < M)
                *(float2*)(C + (size_t)r * N + c) = make_float2(a4[0] + b0, a4[1] + b1);
            if (r + 8 < M)
                *(float2*)(C + (size_t)(r + 8) * N + c) = make_float2(a4[2] + b0, a4[3] + b1);
        }
    }
}

__global__ void __launch_bounds__(256, 2) qkv_gemm_tf32(
    const float* __restrict__ x,
    const float* __restrict__ Wq, const float* __restrict__ bq,
    const float* __restrict__ Wk, const float* __restrict__ bk,
    const float* __restrict__ Wv, const float* __restrict__ bv)
{
    __shared__ uint32_t As[2 * 128 * GSTR];
    __shared__ uint32_t Bs[2 * GM_BN * GSTR];
    const float* W; const float* b; float* out;
    if (blockIdx.z == 0)      { W = Wq; b = bq; out = g_q; }
    else if (blockIdx.z == 1) { W = Wk; b = bk; out = g_k; }
    else                      { W = Wv; b = bv; out = g_v; }
    gemm_tile_tf32<128>(x, W, b, out, LTOK, DIM, DIM,
                        blockIdx.y * 128, blockIdx.x * GM_BN, As, Bs);
}

__global__ void __launch_bounds__(256, 2) out_gemm_tf32(
    const float* __restrict__ Wo, const float* __restrict__ bo,
    float* __restrict__ out)
{
    __shared__ uint32_t As[2 * 64 * GSTR];
    __shared__ uint32_t Bs[2 * GM_BN * GSTR];
    gemm_tile_tf32<64>(g_o, Wo, bo, out, LTOK, DIM, DIM,
                       blockIdx.y * 64, blockIdx.x * GM_BN, As, Bs);
}

// ================= fused RMSNorm + RoPE (q and k) =================
__global__ void __launch_bounds__(256) rmsnorm_rope(
    const float* __restrict__ gq, const float* __restrict__ gk,
    const float* __restrict__ freqs, const int* __restrict__ gsz)
{
    const int t = blockIdx.x;
    const int which = blockIdx.y;
    float* row = (which ? g_k : g_q) + (size_t)t * DIM;
    const float* g = which ? gk : gq;
    const int tid = threadIdx.x;

    float ss = 0.f;
    for (int i = tid; i < DIM; i += 256) {
        float v = row[i];
        ss += v * v;
    }
    __shared__ float red[8];
#pragma unroll
    for (int o = 16; o; o >>= 1) ss += __shfl_xor_sync(0xffffffffu, ss, o);
    if ((tid & 31) == 0) red[tid >> 5] = ss;
    __syncthreads();
    if (tid < 8) {
        float v = red[tid];
#pragma unroll
        for (int o = 4; o; o >>= 1) v += __shfl_xor_sync(0xffu, v, o);
        if (tid == 0) red[0] = v;
    }
    __syncthreads();
    const float rms = rsqrtf(red[0] * (1.0f / DIM) + EPS);

    const int Hs = gsz[1], Ws = gsz[2];
    const int fi = t / (Hs * Ws);
    const int hi = (t / Ws) % Hs;
    const int wi = t % Ws;

    for (int p = tid; p < HEADS * 64; p += 256) {
        const int h = p >> 6;
        const int j = p & 63;
        const int pos = (j < 22) ? fi : ((j < 43) ? hi : wi);
        const float ang = freqs[pos * 64 + j];
        float c, s;
        sincosf(ang, &s, &c);
        const int d0 = h * HD + 2 * j;
        const float x0 = row[d0]     * rms * g[d0];
        const float x1 = row[d0 + 1] * rms * g[d0 + 1];
        row[d0]     = x0 * c - x1 * s;
        row[d0 + 1] = x0 * s + x1 * c;
    }
}

// ================= flash attention (tf32 mma, reg-staged K/V prefetch) ====
#define FQ 64
#define FK 64
#define QST 132     // %32 = 4  -> conflict-free row-varying frag loads
#define KST 132     // K phase stride (row varies with lane>>2)
#define VST 136     // %32 = 8  -> conflict-free PV B-frags (row varies with lane&3)
#define SST 68      // %32 = 4
#define FLASH_SMEM_FLOATS (FQ * QST + FK * VST + FQ * SST + 3 * FQ)

__global__ void __launch_bounds__(256, 2) flash_tf32()
{
    extern __shared__ float sm[];
    float* Qs  = sm;
    float* KVs = Qs + FQ * QST;
    float* Ss  = KVs + FK * VST;
    float* m_s = Ss + FQ * SST;
    float* l_s = m_s + FQ;
    float* f_s = l_s + FQ;
    uint32_t* Qu  = (uint32_t*)Qs;
    uint32_t* KVu = (uint32_t*)KVs;
    uint32_t* Su  = (uint32_t*)Ss;

    const int tid = threadIdx.x;
    const int lane = tid & 31;
    const int wid = tid >> 5;
    const int wm = wid >> 2;
    const int wn = wid & 3;
    const int h  = blockIdx.y;
    const int q0 = blockIdx.x * FQ;

    int srow[8], scol[8];
#pragma unroll
    for (int j = 0; j < 8; ++j) {
        int i = tid + j * 256;
        srow[j] = i >> 5;
        scol[j] = (i & 31) * 4;
    }

#pragma unroll
    for (int j = 0; j < 8; ++j) {
        float4 v = *(const float4*)(g_q + (size_t)(q0 + srow[j]) * DIM + h * HD + scol[j]);
        uint32_t* p = &Qu[srow[j] * QST + scol[j]];
        p[0] = f2tf(v.x * SCALE); p[1] = f2tf(v.y * SCALE);
        p[2] = f2tf(v.z * SCALE); p[3] = f2tf(v.w * SCALE);
    }
    if (tid < FQ) { m_s[tid] = -3.0e38f; l_s[tid] = 0.f; }

    float O[8][4];
#pragma unroll
    for (int t = 0; t < 8; ++t) O[t][0] = O[t][1] = O[t][2] = O[t][3] = 0.f;

    float4 kreg[8];
#pragma unroll
    for (int j = 0; j < 8; ++j)
        kreg[j] = *(const float4*)(g_k + (size_t)srow[j] * DIM + h * HD + scol[j]);

    for (int t0 = 0; t0 < LTOK; t0 += FK) {
        __syncthreads();   // (1) prev PV reads of KVs done
        // commit K(t) registers -> smem (stride KST)
#pragma unroll
        for (int j = 0; j < 8; ++j) {
            uint32_t* p = &KVu[srow[j] * KST + scol[j]];
            p[0] = f2tf(kreg[j].x); p[1] = f2tf(kreg[j].y);
            p[2] = f2tf(kreg[j].z); p[3] = f2tf(kreg[j].w);
        }
        __syncthreads();   // (2) K visible

        // issue V(t) loads early
        float4 vreg[8];
#pragma unroll
        for (int j = 0; j < 8; ++j)
            vreg[j] = *(const float4*)(g_v + (size_t)(t0 + srow[j]) * DIM + h * HD + scol[j]);

        // S = Q K^T : warp tile 32(q) x 16(kv)
        float Sacc[2][2][4] = {};
#pragma unroll
        for (int ks = 0; ks < 16; ++ks) {
            const int kb = ks * 8;
            uint32_t af[2][4], bf[2][2];
#pragma unroll
            for (int mt = 0; mt < 2; ++mt) {
                int r = wm * 32 + mt * 16 + (lane >> 2);
                af[mt][0] = Qu[r * QST + kb + (lane & 3)];
                af[mt][1] = Qu[(r + 8) * QST + kb + (lane & 3)];
                af[mt][2] = Qu[r * QST + kb + (lane & 3) + 4];
                af[mt][3] = Qu[(r + 8) * QST + kb + (lane & 3) + 4];
            }
#pragma unroll
            for (int nt = 0; nt < 2; ++nt) {
                int r = wn * 16 + nt * 8 + (lane >> 2);
                bf[nt][0] = KVu[r * KST + kb + (lane & 3)];
                bf[nt][1] = KVu[r * KST + kb + (lane & 3) + 4];
            }
#pragma unroll
            for (int mt = 0; mt < 2; ++mt)
#pragma unroll
                for (int nt = 0; nt < 2; ++nt)
                    mma_tf32(Sacc[mt][nt],
                             af[mt][0], af[mt][1], af[mt][2], af[mt][3],
                             bf[nt][0], bf[nt][1]);
        }
#pragma unroll
        for (int mt = 0; mt < 2; ++mt) {
            int r = wm * 32 + mt * 16 + (lane >> 2);
#pragma unroll
            for (int nt = 0; nt < 2; ++nt) {
                int c = wn * 16 + nt * 8 + (lane & 3) * 2;
                *(float2*)&Ss[r * SST + c] = make_float2(Sacc[mt][nt][0], Sacc[mt][nt][1]);
                *(float2*)&Ss[(r + 8) * SST + c] = make_float2(Sacc[mt][nt][2], Sacc[mt][nt][3]);
            }
        }

        // prefetch K(t+1) into registers
        if (t0 + FK < LTOK) {
#pragma unroll
            for (int j = 0; j < 8; ++j)
                kreg[j] = *(const float4*)(g_k + (size_t)(t0 + FK + srow[j]) * DIM + h * HD + scol[j]);
        }
        __syncthreads();   // (3) Ss visible, KVs free

        // commit V registers -> smem (stride VST)
#pragma unroll
        for (int j = 0; j < 8; ++j) {
            uint32_t* p = &KVu[srow[j] * VST + scol[j]];
            p[0] = f2tf(vreg[j].x); p[1] = f2tf(vreg[j].y);
            p[2] = f2tf(vreg[j].z); p[3] = f2tf(vreg[j].w);
        }

        // online softmax on Ss (column-interleaved per seg: bank-conflict-free)
        {
            const int row = tid >> 2;
            const int seg = tid & 3;
            const float mold = m_s[row];
            float vals[16];
            float tm = -3.0e38f;
#pragma unroll
            for (int c = 0; c < 16; ++c) {
                vals[c] = Ss[row * SST + seg + 4 * c];
                tm = fmaxf(tm, vals[c]);
            }
            tm = fmaxf(tm, __shfl_xor_sync(0xffffffffu, tm, 1));
            tm = fmaxf(tm, __shfl_xor_sync(0xffffffffu, tm, 2));
            const float mnew = fmaxf(mold, tm);
            float psum = 0.f;
#pragma unroll
            for (int c = 0; c < 16; ++c) {
                float p = __expf(vals[c] - mnew);
                psum += p;
                Su[row * SST + seg + 4 * c] = f2tf(p);
            }
            psum += __shfl_xor_sync(0xffffffffu, psum, 1);
            psum += __shfl_xor_sync(0xffffffffu, psum, 2);
            if (seg == 0) {
                float f = __expf(mold - mnew);
                f_s[row] = f;
                l_s[row] = l_s[row] * f + psum;
                m_s[row] = mnew;
            }
        }
        __syncthreads();   // (4) V + Su + f_s visible

        // O = O*f + P @ V : warp tile 32(q) x 32(hd)
#pragma unroll
        for (int mt = 0; mt < 2; ++mt) {
            int r = wm * 32 + mt * 16 + (lane >> 2);
            float f0 = f_s[r], f1 = f_s[r + 8];
#pragma unroll
            for (int nt = 0; nt < 4; ++nt) {
                O[mt * 4 + nt][0] *= f0; O[mt * 4 + nt][1] *= f0;
                O[mt * 4 + nt][2] *= f1; O[mt * 4 + nt][3] *= f1;
            }
        }
#pragma unroll
        for (int ks = 0; ks < 8; ++ks) {
            const int kb = ks * 8;
            uint32_t af[2][4], bf[4][2];
#pragma unroll
            for (int mt = 0; mt < 2; ++mt) {
                int r = wm * 32 + mt * 16 + (lane >> 2);
                af[mt][0] = Su[r * SST + kb + (lane & 3)];
                af[mt][1] = Su[(r + 8) * SST + kb + (lane & 3)];
                af[mt][2] = Su[r * SST + kb + (lane & 3) + 4];
                af[mt][3] = Su[(r + 8) * SST + kb + (lane & 3) + 4];
            }
#pragma unroll
            for (int nt = 0; nt < 4; ++nt) {
                int c = wn * 32 + nt * 8 + (lane >> 2);
                bf[nt][0] = KVu[(kb + (lane & 3)) * VST + c];
                bf[nt][1] = KVu[(kb + (lane & 3) + 4) * VST + c];
            }
#pragma unroll
            for (int mt = 0; mt < 2; ++mt)
#pragma unroll
                for (int nt = 0; nt < 4; ++nt)
                    mma_tf32(O[mt * 4 + nt],
                             af[mt][0], af[mt][1], af[mt][2], af[mt][3],
                             bf[nt][0], bf[nt][1]);
        }
    }

    // finalize
#pragma unroll
    for (int mt = 0; mt < 2; ++mt) {
        int r = wm * 32 + mt * 16 + (lane >> 2);
        float inv0 = 1.f / l_s[r], inv1 = 1.f / l_s[r + 8];
#pragma unroll
        for (int nt = 0; nt < 4; ++nt) {
            int c = wn * 32 + nt * 8 + (lane & 3) * 2;
            float* d0 = g_o + (size_t)(q0 + r) * DIM + h * HD + c;
            *(float2*)d0 = make_float2(O[mt * 4 + nt][0] * inv0, O[mt * 4 + nt][1] * inv0);
            float* d1 = g_o + (size_t)(q0 + r + 8) * DIM + h * HD + c;
            *(float2*)d1 = make_float2(O[mt * 4 + nt][2] * inv1, O[mt * 4 + nt][3] * inv1);
        }
    }
}

// ================= launch =================
extern "C" void kernel_launch(void* const* d_in, const int* in_sizes, int n_in,
                              void* d_out, int out_size)
{
    const float* x          = (const float*)d_in[0];
    const int*   grid_sizes = (const int*)d_in[2];
    const float* freqs      = (const float*)d_in[3];
    const float* Wq = (const float*)d_in[4];
    const float* bq = (const float*)d_in[5];
    const float* Wk = (const float*)d_in[6];
    const float* bk = (const float*)d_in[7];
    const float* Wv = (const float*)d_in[8];
    const float* bv = (const float*)d_in[9];
    const float* Wo = (const float*)d_in[10];
    const float* bo = (const float*)d_in[11];
    const float* gq = (const float*)d_in[12];
    const float* gk = (const float*)d_in[13];
    float* out = (float*)d_out;

    const int flash_smem = FLASH_SMEM_FLOATS * sizeof(float);
    cudaFuncSetAttribute(flash_tf32, cudaFuncAttributeMaxDynamicSharedMemorySize, flash_smem);

    dim3 gqkv(DIM / GM_BN, (LTOK + 127) / 128, 3);     // 12 x 28 x 3
    dim3 gout(DIM / GM_BN, (LTOK + 63) / 64);          // 12 x 55

    qkv_gemm_tf32<<<gqkv, 256>>>(x, Wq, bq, Wk, bk, Wv, bv);
    rmsnorm_rope<<<dim3(LTOK, 2), 256>>>(gq, gk, freqs, grid_sizes);
    flash_tf32<<<dim3(LTOK / FQ, HEADS), 256, flash_smem>>>();
    out_gemm_tf32<<<gout, 256>>>(Wo, bo, out);
}

// round 8
// speedup vs baseline: 4.6608x; 1.0840x over previous
#include <cuda_runtime.h>
#include <cstdint>

#define DIM    1536
#define HEADS  12
#define HD     128
#define LTOK   3520
#define EPS    1e-6f
#define SCALE  0.08838834764831845f   // 1/sqrt(128)

// ---------------- scratch (no allocation allowed) ----------------
__device__ float g_q[LTOK * DIM];
__device__ float g_k[LTOK * DIM];
__device__ float g_v[LTOK * DIM];
__device__ float g_o[LTOK * DIM];

// ---------------- tf32 / ldmatrix helpers ----------------
__device__ __forceinline__ uint32_t f2tf(float f) {
    uint32_t u;
    asm("cvt.rna.tf32.f32 %0, %1;" : "=r"(u) : "f"(f));
    return u;
}

__device__ __forceinline__ void mma_tf32(float c[4],
    uint32_t a0, uint32_t a1, uint32_t a2, uint32_t a3,
    uint32_t b0, uint32_t b1)
{
    asm volatile(
        "mma.sync.aligned.m16n8k8.row.col.f32.tf32.tf32.f32 "
        "{%0,%1,%2,%3}, {%4,%5,%6,%7}, {%8,%9}, {%0,%1,%2,%3};\n"
        : "+f"(c[0]), "+f"(c[1]), "+f"(c[2]), "+f"(c[3])
        : "r"(a0), "r"(a1), "r"(a2), "r"(a3), "r"(b0), "r"(b1));
}

__device__ __forceinline__ void ldsm_x4(uint32_t& r0, uint32_t& r1,
                                        uint32_t& r2, uint32_t& r3, uint32_t addr)
{
    asm volatile("ldmatrix.sync.aligned.m8n8.x4.shared.b16 {%0,%1,%2,%3}, [%4];"
                 : "=r"(r0), "=r"(r1), "=r"(r2), "=r"(r3) : "r"(addr));
}
__device__ __forceinline__ uint32_t smem_addr(const void* p) {
    return (uint32_t)__cvta_generic_to_shared(p);
}

// ================= tf32 GEMM: C[M,N] = A[M,K] @ B[N,K]^T + bias ==========
// BM=BN=128, BK=16, 256 threads (8 warps as 2x4), warp tile 64x32.
// 2-stage double buffer; fragment loads via ldmatrix.x4.
#define GM_BM 128
#define GM_BN 128
#define GM_BK 16
#define GSTR  20   // row stride in words (80B = 5*16B): LDSM rows partition all 32 banks
#define GM_STAGE (GM_BM * GSTR)

__device__ __forceinline__ void gemm_tile_tf32(
    const float* __restrict__ A, const float* __restrict__ B,
    const float* __restrict__ bias, float* __restrict__ C,
    int M, int N, int K, int m0, int n0,
    uint32_t* As, uint32_t* Bs)
{
    const int tid = threadIdx.x;
    const int lane = tid & 31;
    const int wid = tid >> 5;
    const int wm = wid >> 2;       // 0..1
    const int wn = wid & 3;        // 0..3

    // ldmatrix per-thread address components
    const int tr = lane & 7;
    const int mq = lane >> 3;                  // matrix index 0..3
    const int a_row = tr + 8 * (mq & 1);       // A-side: rows split by m&1
    const int a_ko  = 4 * (mq >> 1);           //          k half by m>>1
    const int b_row = tr + 8 * (mq >> 1);      // B-side pair: rows by m>>1
    const int b_ko  = 4 * (mq & 1);            //          k half by m&1

    int arow[2], brow[2], kc[2], sr[2];
#pragma unroll
    for (int i = 0; i < 2; ++i) {
        int s = tid + i * 256;
        sr[i] = s >> 2;
        kc[i] = (s & 3) * 4;
        arow[i] = min(m0 + sr[i], M - 1);
        brow[i] = n0 + sr[i];
    }

    float4 areg[2], breg[2];
#pragma unroll
    for (int i = 0; i < 2; ++i) {
        areg[i] = *(const float4*)(A + (size_t)arow[i] * K + kc[i]);
        breg[i] = *(const float4*)(B + (size_t)brow[i] * K + kc[i]);
    }
#pragma unroll
    for (int i = 0; i < 2; ++i) {
        uint32_t* pa = &As[sr[i] * GSTR + kc[i]];
        pa[0] = f2tf(areg[i].x); pa[1] = f2tf(areg[i].y);
        pa[2] = f2tf(areg[i].z); pa[3] = f2tf(areg[i].w);
        uint32_t* pb = &Bs[sr[i] * GSTR + kc[i]];
        pb[0] = f2tf(breg[i].x); pb[1] = f2tf(breg[i].y);
        pb[2] = f2tf(breg[i].z); pb[3] = f2tf(breg[i].w);
    }
    __syncthreads();

    float acc[16][4];
#pragma unroll
    for (int t = 0; t < 16; ++t)
        acc[t][0] = acc[t][1] = acc[t][2] = acc[t][3] = 0.f;

    const uint32_t As_u = smem_addr(As);
    const uint32_t Bs_u = smem_addr(Bs);

    int buf = 0;
    for (int k0 = 0; k0 < K; k0 += GM_BK) {
        const bool has_next = (k0 + GM_BK < K);
        if (has_next) {
#pragma unroll
            for (int i = 0; i < 2; ++i) {
                areg[i] = *(const float4*)(A + (size_t)arow[i] * K + k0 + GM_BK + kc[i]);
                breg[i] = *(const float4*)(B + (size_t)brow[i] * K + k0 + GM_BK + kc[i]);
            }
        }

        const uint32_t Ab = As_u + 4u * (buf * GM_STAGE);
        const uint32_t Bb = Bs_u + 4u * (buf * GM_STAGE);
#pragma unroll
        for (int ks = 0; ks < 2; ++ks) {
            const int kb = ks * 8;
            uint32_t af[4][4], bf[4][2];
#pragma unroll
            for (int mt = 0; mt < 4; ++mt) {
                uint32_t addr = Ab + 4u * ((wm * 64 + mt * 16 + a_row) * GSTR + kb + a_ko);
                ldsm_x4(af[mt][0], af[mt][1], af[mt][2], af[mt][3], addr);
            }
#pragma unroll
            for (int p = 0; p < 2; ++p) {
                uint32_t addr = Bb + 4u * ((wn * 32 + p * 16 + b_row) * GSTR + kb + b_ko);
                ldsm_x4(bf[2*p][0], bf[2*p][1], bf[2*p+1][0], bf[2*p+1][1], addr);
            }
#pragma unroll
            for (int mt = 0; mt < 4; ++mt)
#pragma unroll
                for (int nt = 0; nt < 4; ++nt)
                    mma_tf32(acc[mt * 4 + nt],
                             af[mt][0], af[mt][1], af[mt][2], af[mt][3],
                             bf[nt][0], bf[nt][1]);
        }

        if (has_next) {
            uint32_t* An = As + (buf ^ 1) * GM_STAGE;
            uint32_t* Bn = Bs + (buf ^ 1) * GM_STAGE;
#pragma unroll
            for (int i = 0; i < 2; ++i) {
                uint32_t* pa = &An[sr[i] * GSTR + kc[i]];
                pa[0] = f2tf(areg[i].x); pa[1] = f2tf(areg[i].y);
                pa[2] = f2tf(areg[i].z); pa[3] = f2tf(areg[i].w);
                uint32_t* pb = &Bn[sr[i] * GSTR + kc[i]];
                pb[0] = f2tf(breg[i].x); pb[1] = f2tf(breg[i].y);
                pb[2] = f2tf(breg[i].z); pb[3] = f2tf(breg[i].w);
            }
        }
        __syncthreads();
        buf ^= 1;
    }

    // epilogue
#pragma unroll
    for (int nt = 0; nt < 4; ++nt) {
        int c = n0 + wn * 32 + nt * 8 + (lane & 3) * 2;
        float b0 = bias[c], b1 = bias[c + 1];
#pragma unroll
        for (int mt = 0; mt < 4; ++mt) {
            int r = m0 + wm * 64 + mt * 16 + (lane >> 2);
            float* a4 = acc[mt * 4 + nt];
            if (r < M)
                *(float2*)(C + (size_t)r * N + c) = make_float2(a4[0] + b0, a4[1] + b1);
            if (r + 8 < M)
                *(float2*)(C + (size_t)(r + 8) * N + c) = make_float2(a4[2] + b0, a4[3] + b1);
        }
    }
}

__global__ void __launch_bounds__(256, 2) qkv_gemm_tf32(
    const float* __restrict__ x,
    const float* __restrict__ Wq, const float* __restrict__ bq,
    const float* __restrict__ Wk, const float* __restrict__ bk,
    const float* __restrict__ Wv, const float* __restrict__ bv)
{
    __shared__ __align__(16) uint32_t As[2 * GM_STAGE];
    __shared__ __align__(16) uint32_t Bs[2 * GM_STAGE];
    const float* W; const float* b; float* out;
    if (blockIdx.z == 0)      { W = Wq; b = bq; out = g_q; }
    else if (blockIdx.z == 1) { W = Wk; b = bk; out = g_k; }
    else                      { W = Wv; b = bv; out = g_v; }
    gemm_tile_tf32(x, W, b, out, LTOK, DIM, DIM,
                   blockIdx.y * GM_BM, blockIdx.x * GM_BN, As, Bs);
}

__global__ void __launch_bounds__(256, 2) out_gemm_tf32(
    const float* __restrict__ Wo, const float* __restrict__ bo,
    float* __restrict__ out)
{
    __shared__ __align__(16) uint32_t As[2 * GM_STAGE];
    __shared__ __align__(16) uint32_t Bs[2 * GM_STAGE];
    gemm_tile_tf32(g_o, Wo, bo, out, LTOK, DIM, DIM,
                   blockIdx.y * GM_BM, blockIdx.x * GM_BN, As, Bs);
}

// ================= fused RMSNorm + RoPE (q and k) =================
__global__ void __launch_bounds__(256) rmsnorm_rope(
    const float* __restrict__ gq, const float* __restrict__ gk,
    const float* __restrict__ freqs, const int* __restrict__ gsz)
{
    const int t = blockIdx.x;
    const int which = blockIdx.y;
    float* row = (which ? g_k : g_q) + (size_t)t * DIM;
    const float* g = which ? gk : gq;
    const int tid = threadIdx.x;

    float ss = 0.f;
    for (int i = tid; i < DIM; i += 256) {
        float v = row[i];
        ss += v * v;
    }
    __shared__ float red[8];
#pragma unroll
    for (int o = 16; o; o >>= 1) ss += __shfl_xor_sync(0xffffffffu, ss, o);
    if ((tid & 31) == 0) red[tid >> 5] = ss;
    __syncthreads();
    if (tid < 8) {
        float v = red[tid];
#pragma unroll
        for (int o = 4; o; o >>= 1) v += __shfl_xor_sync(0xffu, v, o);
        if (tid == 0) red[0] = v;
    }
    __syncthreads();
    const float rms = rsqrtf(red[0] * (1.0f / DIM) + EPS);

    const int Hs = gsz[1], Ws = gsz[2];
    const int fi = t / (Hs * Ws);
    const int hi = (t / Ws) % Hs;
    const int wi = t % Ws;

    for (int p = tid; p < HEADS * 64; p += 256) {
        const int h = p >> 6;
        const int j = p & 63;
        const int pos = (j < 22) ? fi : ((j < 43) ? hi : wi);
        const float ang = freqs[pos * 64 + j];
        float c, s;
        sincosf(ang, &s, &c);
        const int d0 = h * HD + 2 * j;
        const float x0 = row[d0]     * rms * g[d0];
        const float x1 = row[d0 + 1] * rms * g[d0 + 1];
        row[d0]     = x0 * c - x1 * s;
        row[d0 + 1] = x0 * s + x1 * c;
    }
}

// ================= flash attention (tf32 mma + ldmatrix) =================
#define FQ 64
#define FK 64
#define QST 132     // 528B rows (33*16); %32=4 -> LDSM rows partition banks
#define KST 132
#define VST 136     // %32=8 -> conflict-free PV scalar B-frags
#define SST 68      // 272B rows (17*16); %32=4
#define FLASH_SMEM_FLOATS (FQ * QST + FK * VST + FQ * SST + 3 * FQ)

__global__ void __launch_bounds__(256, 2) flash_tf32()
{
    extern __shared__ float sm[];
    float* Qs  = sm;
    float* KVs = Qs + FQ * QST;
    float* Ss  = KVs + FK * VST;
    float* m_s = Ss + FQ * SST;
    float* l_s = m_s + FQ;
    float* f_s = l_s + FQ;
    uint32_t* Qu  = (uint32_t*)Qs;
    uint32_t* KVu = (uint32_t*)KVs;
    uint32_t* Su  = (uint32_t*)Ss;

    const int tid = threadIdx.x;
    const int lane = tid & 31;
    const int wid = tid >> 5;
    const int wm = wid >> 2;
    const int wn = wid & 3;
    const int h  = blockIdx.y;
    const int q0 = blockIdx.x * FQ;

    const int tr = lane & 7;
    const int mq = lane >> 3;
    const int a_row = tr + 8 * (mq & 1);
    const int a_ko  = 4 * (mq >> 1);
    const int b_row = tr + 8 * (mq >> 1);
    const int b_ko  = 4 * (mq & 1);

    const uint32_t Qa = smem_addr(Qu);
    const uint32_t Ka = smem_addr(KVu);
    const uint32_t Sa = smem_addr(Su);

    int srow[8], scol[8];
#pragma unroll
    for (int j = 0; j < 8; ++j) {
        int i = tid + j * 256;
        srow[j] = i >> 5;
        scol[j] = (i & 31) * 4;
    }

#pragma unroll
    for (int j = 0; j < 8; ++j) {
        float4 v = *(const float4*)(g_q + (size_t)(q0 + srow[j]) * DIM + h * HD + scol[j]);
        uint32_t* p = &Qu[srow[j] * QST + scol[j]];
        p[0] = f2tf(v.x * SCALE); p[1] = f2tf(v.y * SCALE);
        p[2] = f2tf(v.z * SCALE); p[3] = f2tf(v.w * SCALE);
    }
    if (tid < FQ) { m_s[tid] = -3.0e38f; l_s[tid] = 0.f; }

    float O[8][4];
#pragma unroll
    for (int t = 0; t < 8; ++t) O[t][0] = O[t][1] = O[t][2] = O[t][3] = 0.f;

    float4 kreg[8];
#pragma unroll
    for (int j = 0; j < 8; ++j)
        kreg[j] = *(const float4*)(g_k + (size_t)srow[j] * DIM + h * HD + scol[j]);

    for (int t0 = 0; t0 < LTOK; t0 += FK) {
        __syncthreads();   // (1) prev PV reads done
#pragma unroll
        for (int j = 0; j < 8; ++j) {
            uint32_t* p = &KVu[srow[j] * KST + scol[j]];
            p[0] = f2tf(kreg[j].x); p[1] = f2tf(kreg[j].y);
            p[2] = f2tf(kreg[j].z); p[3] = f2tf(kreg[j].w);
        }
        __syncthreads();   // (2) K visible

        float4 vreg[8];
#pragma unroll
        for (int j = 0; j < 8; ++j)
            vreg[j] = *(const float4*)(g_v + (size_t)(t0 + srow[j]) * DIM + h * HD + scol[j]);

        // S = Q K^T : warp tile 32(q) x 16(kv)
        float Sacc[2][2][4] = {};
#pragma unroll
        for (int ks = 0; ks < 16; ++ks) {
            const int kb = ks * 8;
            uint32_t af[2][4], bf[2][2];
#pragma unroll
            for (int mt = 0; mt < 2; ++mt) {
                uint32_t addr = Qa + 4u * ((wm * 32 + mt * 16 + a_row) * QST + kb + a_ko);
                ldsm_x4(af[mt][0], af[mt][1], af[mt][2], af[mt][3], addr);
            }
            {
                uint32_t addr = Ka + 4u * ((wn * 16 + b_row) * KST + kb + b_ko);
                ldsm_x4(bf[0][0], bf[0][1], bf[1][0], bf[1][1], addr);
            }
#pragma unroll
            for (int mt = 0; mt < 2; ++mt)
#pragma unroll
                for (int nt = 0; nt < 2; ++nt)
                    mma_tf32(Sacc[mt][nt],
                             af[mt][0], af[mt][1], af[mt][2], af[mt][3],
                             bf[nt][0], bf[nt][1]);
        }
#pragma unroll
        for (int mt = 0; mt < 2; ++mt) {
            int r = wm * 32 + mt * 16 + (lane >> 2);
#pragma unroll
            for (int nt = 0; nt < 2; ++nt) {
                int c = wn * 16 + nt * 8 + (lane & 3) * 2;
                *(float2*)&Ss[r * SST + c] = make_float2(Sacc[mt][nt][0], Sacc[mt][nt][1]);
                *(float2*)&Ss[(r + 8) * SST + c] = make_float2(Sacc[mt][nt][2], Sacc[mt][nt][3]);
            }
        }

        if (t0 + FK < LTOK) {
#pragma unroll
            for (int j = 0; j < 8; ++j)
                kreg[j] = *(const float4*)(g_k + (size_t)(t0 + FK + srow[j]) * DIM + h * HD + scol[j]);
        }
        __syncthreads();   // (3) Ss visible, KVs free

#pragma unroll
        for (int j = 0; j < 8; ++j) {
            uint32_t* p = &KVu[srow[j] * VST + scol[j]];
            p[0] = f2tf(vreg[j].x); p[1] = f2tf(vreg[j].y);
            p[2] = f2tf(vreg[j].z); p[3] = f2tf(vreg[j].w);
        }

        // online softmax (column-interleaved per seg)
        {
            const int row = tid >> 2;
            const int seg = tid & 3;
            const float mold = m_s[row];
            float vals[16];
            float tm = -3.0e38f;
#pragma unroll
            for (int c = 0; c < 16; ++c) {
                vals[c] = Ss[row * SST + seg + 4 * c];
                tm = fmaxf(tm, vals[c]);
            }
            tm = fmaxf(tm, __shfl_xor_sync(0xffffffffu, tm, 1));
            tm = fmaxf(tm, __shfl_xor_sync(0xffffffffu, tm, 2));
            const float mnew = fmaxf(mold, tm);
            float psum = 0.f;
#pragma unroll
            for (int c = 0; c < 16; ++c) {
                float p = __expf(vals[c] - mnew);
                psum += p;
                Su[row * SST + seg + 4 * c] = f2tf(p);
            }
            psum += __shfl_xor_sync(0xffffffffu, psum, 1);
            psum += __shfl_xor_sync(0xffffffffu, psum, 2);
            if (seg == 0) {
                float f = __expf(mold - mnew);
                f_s[row] = f;
                l_s[row] = l_s[row] * f + psum;
                m_s[row] = mnew;
            }
        }
        __syncthreads();   // (4) V + Su + f_s visible

        // O = O*f + P @ V : warp tile 32(q) x 32(hd)
#pragma unroll
        for (int mt = 0; mt < 2; ++mt) {
            int r = wm * 32 + mt * 16 + (lane >> 2);
            float f0 = f_s[r], f1 = f_s[r + 8];
#pragma unroll
            for (int nt = 0; nt < 4; ++nt) {
                O[mt * 4 + nt][0] *= f0; O[mt * 4 + nt][1] *= f0;
                O[mt * 4 + nt][2] *= f1; O[mt * 4 + nt][3] *= f1;
            }
        }
#pragma unroll
        for (int ks = 0; ks < 8; ++ks) {
            const int kb = ks * 8;
            uint32_t af[2][4], bf[4][2];
#pragma unroll
            for (int mt = 0; mt < 2; ++mt) {
                uint32_t addr = Sa + 4u * ((wm * 32 + mt * 16 + a_row) * SST + kb + a_ko);
                ldsm_x4(af[mt][0], af[mt][1], af[mt][2], af[mt][3], addr);
            }
#pragma unroll
            for (int nt = 0; nt < 4; ++nt) {
                int c = wn * 32 + nt * 8 + (lane >> 2);
                bf[nt][0] = KVu[(kb + (lane & 3)) * VST + c];
                bf[nt][1] = KVu[(kb + (lane & 3) + 4) * VST + c];
            }
#pragma unroll
            for (int mt = 0; mt < 2; ++mt)
#pragma unroll
                for (int nt = 0; nt < 4; ++nt)
                    mma_tf32(O[mt * 4 + nt],
                             af[mt][0], af[mt][1], af[mt][2], af[mt][3],
                             bf[nt][0], bf[nt][1]);
        }
    }

    // finalize
#pragma unroll
    for (int mt = 0; mt < 2; ++mt) {
        int r = wm * 32 + mt * 16 + (lane >> 2);
        float inv0 = 1.f / l_s[r], inv1 = 1.f / l_s[r + 8];
#pragma unroll
        for (int nt = 0; nt < 4; ++nt) {
            int c = wn * 32 + nt * 8 + (lane & 3) * 2;
            float* d0 = g_o + (size_t)(q0 + r) * DIM + h * HD + c;
            *(float2*)d0 = make_float2(O[mt * 4 + nt][0] * inv0, O[mt * 4 + nt][1] * inv0);
            float* d1 = g_o + (size_t)(q0 + r + 8) * DIM + h * HD + c;
            *(float2*)d1 = make_float2(O[mt * 4 + nt][2] * inv1, O[mt * 4 + nt][3] * inv1);
        }
    }
}

// ================= launch =================
extern "C" void kernel_launch(void* const* d_in, const int* in_sizes, int n_in,
                              void* d_out, int out_size)
{
    const float* x          = (const float*)d_in[0];
    const int*   grid_sizes = (const int*)d_in[2];
    const float* freqs      = (const float*)d_in[3];
    const float* Wq = (const float*)d_in[4];
    const float* bq = (const float*)d_in[5];
    const float* Wk = (const float*)d_in[6];
    const float* bk = (const float*)d_in[7];
    const float* Wv = (const float*)d_in[8];
    const float* bv = (const float*)d_in[9];
    const float* Wo = (const float*)d_in[10];
    const float* bo = (const float*)d_in[11];
    const float* gq = (const float*)d_in[12];
    const float* gk = (const float*)d_in[13];
    float* out = (float*)d_out;

    const int flash_smem = FLASH_SMEM_FLOATS * sizeof(float);
    cudaFuncSetAttribute(flash_tf32, cudaFuncAttributeMaxDynamicSharedMemorySize, flash_smem);

    dim3 gqkv(DIM / GM_BN, (LTOK + GM_BM - 1) / GM_BM, 3);   // 12 x 28 x 3
    dim3 gout(DIM / GM_BN, (LTOK + GM_BM - 1) / GM_BM);      // 12 x 28

    qkv_gemm_tf32<<<gqkv, 256>>>(x, Wq, bq, Wk, bk, Wv, bv);
    rmsnorm_rope<<<dim3(LTOK, 2), 256>>>(gq, gk, freqs, grid_sizes);
    flash_tf32<<<dim3(LTOK / FQ, HEADS), 256, flash_smem>>>();
    out_gemm_tf32<<<gout, 256>>>(Wo, bo, out);
}